// round 1
// baseline (speedup 1.0000x reference)
#include <cuda_runtime.h>
#include <cstdint>

#define N_NODES 50000
#define N_EDGES 800000
#define NFEAT   512
#define NHID    256
#define NCLASS  64

// ---------------- scratch (static device globals; no runtime allocation) ----
__device__ float g_XW1[N_NODES * NHID];     // 51.2 MB
__device__ float g_H  [N_NODES * NHID];     // 51.2 MB
__device__ float g_HW2[N_NODES * NCLASS];   // 12.8 MB
__device__ int   g_counts [N_NODES];
__device__ int   g_row_ptr[N_NODES + 1];
__device__ int   g_cursor [N_NODES];
__device__ int   g_src_sorted[N_EDGES];
__device__ float g_w_sorted  [N_EDGES];

// ---------------- CSR build -------------------------------------------------
__global__ void zero_counts_k() {
    int i = blockIdx.x * blockDim.x + threadIdx.x;
    if (i < N_NODES) g_counts[i] = 0;
}

__global__ void hist_k(const int* __restrict__ edst) {
    int i = blockIdx.x * blockDim.x + threadIdx.x;
    if (i < N_EDGES) atomicAdd(&g_counts[edst[i]], 1);
}

// single-block scan over 50000 counts -> row_ptr (exclusive) + cursor copy
__global__ __launch_bounds__(1024) void scan_k() {
    __shared__ int part[1024];
    const int CH = 49;                       // 1024*49 = 50176 >= 50000
    int t = threadIdx.x;
    int begin = t * CH;
    int end = begin + CH; if (end > N_NODES) end = N_NODES;
    int s = 0;
    for (int i = begin; i < end; i++) s += g_counts[i];
    part[t] = s;
    __syncthreads();
    // Hillis-Steele inclusive scan
    for (int off = 1; off < 1024; off <<= 1) {
        int v = (t >= off) ? part[t - off] : 0;
        __syncthreads();
        part[t] += v;
        __syncthreads();
    }
    int run = (t == 0) ? 0 : part[t - 1];
    for (int i = begin; i < end; i++) {
        g_row_ptr[i] = run;
        g_cursor[i]  = run;
        run += g_counts[i];
    }
    if (t == 1023) g_row_ptr[N_NODES] = part[1023];
}

__global__ void scatter_k(const int* __restrict__ esrc,
                          const int* __restrict__ edst,
                          const float* __restrict__ ew) {
    int i = blockIdx.x * blockDim.x + threadIdx.x;
    if (i < N_EDGES) {
        int d = edst[i];
        int p = atomicAdd(&g_cursor[d], 1);
        g_src_sorted[p] = esrc[i];
        g_w_sorted[p]   = ew[i];
    }
}

// ---------------- SGEMM: C[M,N] = A[M,K] @ B[K,N] ---------------------------
// BM=128, BN=64, BK=16, 256 threads, 8x4 per thread.
__global__ __launch_bounds__(256) void sgemm_k(const float* __restrict__ A,
                                               const float* __restrict__ B,
                                               float* __restrict__ C,
                                               int M, int N, int K) {
    const int BM = 128, BN = 64, BK = 16;
    __shared__ float As[BK][BM + 4];
    __shared__ float Bs[BK][BN];

    int tid  = threadIdx.x;
    int brow = blockIdx.y * BM;
    int bcol = blockIdx.x * BN;

    int tx = tid & 15;            // 0..15  (BN/4)
    int ty = tid >> 4;            // 0..15  (BM/8)
    int arow  = tid >> 2;         // 0..63
    int acol  = (tid & 3) << 2;   // 0,4,8,12
    int browB = tid >> 4;         // 0..15
    int bcolB = (tid & 15) << 2;  // 0..60

    float acc[8][4];
#pragma unroll
    for (int i = 0; i < 8; i++)
#pragma unroll
        for (int j = 0; j < 4; j++) acc[i][j] = 0.f;

    for (int k0 = 0; k0 < K; k0 += BK) {
#pragma unroll
        for (int r = 0; r < 2; r++) {
            int row = brow + arow + r * 64;
            float4 v = make_float4(0.f, 0.f, 0.f, 0.f);
            if (row < M)
                v = *(const float4*)(A + (size_t)row * K + k0 + acol);
            As[acol + 0][arow + r * 64] = v.x;
            As[acol + 1][arow + r * 64] = v.y;
            As[acol + 2][arow + r * 64] = v.z;
            As[acol + 3][arow + r * 64] = v.w;
        }
        *(float4*)(&Bs[browB][bcolB]) =
            *(const float4*)(B + (size_t)(k0 + browB) * N + bcol + bcolB);
        __syncthreads();

#pragma unroll
        for (int k = 0; k < BK; k++) {
            float a[8], b[4];
#pragma unroll
            for (int i = 0; i < 8; i++) a[i] = As[k][ty * 8 + i];
#pragma unroll
            for (int j = 0; j < 4; j++) b[j] = Bs[k][tx * 4 + j];
#pragma unroll
            for (int i = 0; i < 8; i++)
#pragma unroll
                for (int j = 0; j < 4; j++) acc[i][j] += a[i] * b[j];
        }
        __syncthreads();
    }

#pragma unroll
    for (int i = 0; i < 8; i++) {
        int row = brow + ty * 8 + i;
        if (row < M) {
            float4 v = make_float4(acc[i][0], acc[i][1], acc[i][2], acc[i][3]);
            *(float4*)(C + (size_t)row * N + bcol + tx * 4) = v;
        }
    }
}

// ---------------- SpMM layer 1: H = relu(A @ XW1 + b1) ----------------------
// one block per dst node, 256 threads = 256 features (coalesced row gathers)
__global__ __launch_bounds__(256) void spmm1_k(const float* __restrict__ b1) {
    int node = blockIdx.x;
    int f = threadIdx.x;
    int s = g_row_ptr[node], e = g_row_ptr[node + 1];
    float acc = 0.f;
    for (int i = s; i < e; i++) {
        int   src = __ldg(&g_src_sorted[i]);
        float w   = __ldg(&g_w_sorted[i]);
        acc += w * __ldg(&g_XW1[(size_t)src * NHID + f]);
    }
    float v = acc + b1[f];
    g_H[(size_t)node * NHID + f] = fmaxf(v, 0.f);
}

// ---------------- SpMM layer 2 fused with bias + log_softmax ----------------
// 4 nodes per 256-thread block; 64 threads (2 warps) per node
__global__ __launch_bounds__(256) void spmm2_lsm_k(const float* __restrict__ b2,
                                                   float* __restrict__ out) {
    int grp  = threadIdx.x >> 6;   // 0..3
    int f    = threadIdx.x & 63;
    int node = blockIdx.x * 4 + grp;

    int s = g_row_ptr[node], e = g_row_ptr[node + 1];
    float acc = 0.f;
    for (int i = s; i < e; i++) {
        int   src = __ldg(&g_src_sorted[i]);
        float w   = __ldg(&g_w_sorted[i]);
        acc += w * __ldg(&g_HW2[(size_t)src * NCLASS + f]);
    }
    float logit = acc + b2[f];

    // max over the node's 64 lanes (2 warps)
    float m = logit;
#pragma unroll
    for (int o = 16; o > 0; o >>= 1) m = fmaxf(m, __shfl_xor_sync(0xffffffffu, m, o));
    __shared__ float sh_max[8];
    int warp = threadIdx.x >> 5;
    if ((threadIdx.x & 31) == 0) sh_max[warp] = m;
    __syncthreads();
    m = fmaxf(sh_max[grp * 2], sh_max[grp * 2 + 1]);

    float ex = __expf(logit - m);
    float sum = ex;
#pragma unroll
    for (int o = 16; o > 0; o >>= 1) sum += __shfl_xor_sync(0xffffffffu, sum, o);
    __shared__ float sh_sum[8];
    if ((threadIdx.x & 31) == 0) sh_sum[warp] = sum;
    __syncthreads();
    float total = sh_sum[grp * 2] + sh_sum[grp * 2 + 1];

    out[(size_t)node * NCLASS + f] = logit - m - __logf(total);
}

// ---------------- launch ----------------------------------------------------
extern "C" void kernel_launch(void* const* d_in, const int* in_sizes, int n_in,
                              void* d_out, int out_size) {
    const float* x    = (const float*)d_in[0];
    const float* W1   = (const float*)d_in[1];
    const float* b1   = (const float*)d_in[2];
    const float* W2   = (const float*)d_in[3];
    const float* b2   = (const float*)d_in[4];
    const float* ew   = (const float*)d_in[5];
    const int*   esrc = (const int*)d_in[6];
    const int*   edst = (const int*)d_in[7];
    float* out = (float*)d_out;

    float *dXW1, *dH, *dHW2;
    cudaGetSymbolAddress((void**)&dXW1, g_XW1);
    cudaGetSymbolAddress((void**)&dH,   g_H);
    cudaGetSymbolAddress((void**)&dHW2, g_HW2);

    // CSR build (runs every replay; ~50us)
    zero_counts_k<<<(N_NODES + 255) / 256, 256>>>();
    hist_k<<<(N_EDGES + 255) / 256, 256>>>(edst);
    scan_k<<<1, 1024>>>();
    scatter_k<<<(N_EDGES + 255) / 256, 256>>>(esrc, edst, ew);

    // layer 1
    {
        dim3 grid(NHID / 64, (N_NODES + 127) / 128);
        sgemm_k<<<grid, 256>>>(x, W1, dXW1, N_NODES, NHID, NFEAT);
    }
    spmm1_k<<<N_NODES, 256>>>(b1);

    // layer 2
    {
        dim3 grid(NCLASS / 64, (N_NODES + 127) / 128);
        sgemm_k<<<grid, 256>>>(dH, W2, dHW2, N_NODES, NCLASS, NHID);
    }
    spmm2_lsm_k<<<N_NODES / 4, 256>>>(b2, out);
}

// round 3
// speedup vs baseline: 1.1770x; 1.1770x over previous
#include <cuda_runtime.h>
#include <cuda_bf16.h>
#include <cstdint>

#define N_NODES 50000
#define M_PAD   50048      // 391 * 128
#define N_EDGES 800000
#define NFEAT   512
#define NHID    256
#define NCLASS  64
#define K1EXT   (3*NFEAT)  // 1536
#define K2EXT   (3*NHID)   // 768

// ---------------- scratch (static device globals; no runtime allocation) ----
__device__ __align__(256) __nv_bfloat16 g_A1[(size_t)M_PAD * K1EXT];  // 154 MB
__device__ __align__(256) __nv_bfloat16 g_B1[(size_t)NHID * K1EXT];
__device__ __align__(256) __nv_bfloat16 g_A2[(size_t)M_PAD * K2EXT];  // 77 MB
__device__ __align__(256) __nv_bfloat16 g_B2[(size_t)NCLASS * K2EXT];
__device__ __align__(256) float g_XW1[(size_t)N_NODES * NHID];        // 51 MB
__device__ __align__(256) float g_HW2[(size_t)N_NODES * NCLASS];      // 13 MB
__device__ int   g_counts [N_NODES];
__device__ int   g_row_ptr[N_NODES + 1];
__device__ int   g_cursor [N_NODES];
__device__ int   g_src_sorted[N_EDGES];
__device__ float g_w_sorted  [N_EDGES];

// ---------------- helpers ---------------------------------------------------
__device__ __forceinline__ uint32_t smem_u32(const void* p) {
    uint32_t a;
    asm("{ .reg .u64 t; cvta.to.shared.u64 t, %1; cvt.u32.u64 %0, t; }"
        : "=r"(a) : "l"(p));
    return a;
}

// ---------------- CSR build -------------------------------------------------
__global__ void zero_counts_k() {
    int i = blockIdx.x * blockDim.x + threadIdx.x;
    if (i < N_NODES) g_counts[i] = 0;
}

__global__ void hist_k(const int* __restrict__ edst) {
    int i = blockIdx.x * blockDim.x + threadIdx.x;
    if (i < N_EDGES) atomicAdd(&g_counts[edst[i]], 1);
}

__global__ __launch_bounds__(1024) void scan_k() {
    __shared__ int part[1024];
    const int CH = 49;
    int t = threadIdx.x;
    int begin = t * CH;
    int end = begin + CH; if (end > N_NODES) end = N_NODES;
    int s = 0;
    for (int i = begin; i < end; i++) s += g_counts[i];
    part[t] = s;
    __syncthreads();
    for (int off = 1; off < 1024; off <<= 1) {
        int v = (t >= off) ? part[t - off] : 0;
        __syncthreads();
        part[t] += v;
        __syncthreads();
    }
    int run = (t == 0) ? 0 : part[t - 1];
    for (int i = begin; i < end; i++) {
        g_row_ptr[i] = run;
        g_cursor[i]  = run;
        run += g_counts[i];
    }
    if (t == 1023) g_row_ptr[N_NODES] = part[1023];
}

__global__ void scatter_k(const int* __restrict__ esrc,
                          const int* __restrict__ edst,
                          const float* __restrict__ ew) {
    int i = blockIdx.x * blockDim.x + threadIdx.x;
    if (i < N_EDGES) {
        int d = edst[i];
        int p = atomicAdd(&g_cursor[d], 1);
        g_src_sorted[p] = esrc[i];
        g_w_sorted[p]   = ew[i];
    }
}

// ---------------- fp32 -> bf16 split conversions ----------------------------
__global__ void conv_x_k(const float* __restrict__ x) {
    int i = blockIdx.x * blockDim.x + threadIdx.x;
    if (i >= N_NODES * NFEAT) return;
    int m = i / NFEAT, k = i - m * NFEAT;
    float v = x[i];
    __nv_bfloat16 hi = __float2bfloat16(v);
    __nv_bfloat16 lo = __float2bfloat16(v - __bfloat162float(hi));
    size_t base = (size_t)m * K1EXT;
    g_A1[base + k]             = hi;
    g_A1[base + NFEAT + k]     = lo;
    g_A1[base + 2 * NFEAT + k] = hi;
}

__global__ void conv_w1_k(const float* __restrict__ W1) {
    int i = blockIdx.x * blockDim.x + threadIdx.x;
    if (i >= NFEAT * NHID) return;
    int k = i / NHID, n = i - k * NHID;
    float v = W1[i];
    __nv_bfloat16 hi = __float2bfloat16(v);
    __nv_bfloat16 lo = __float2bfloat16(v - __bfloat162float(hi));
    size_t base = (size_t)n * K1EXT;
    g_B1[base + k]             = hi;
    g_B1[base + NFEAT + k]     = hi;
    g_B1[base + 2 * NFEAT + k] = lo;
}

__global__ void conv_w2_k(const float* __restrict__ W2) {
    int i = blockIdx.x * blockDim.x + threadIdx.x;
    if (i >= NHID * NCLASS) return;
    int k = i / NCLASS, n = i - k * NCLASS;
    float v = W2[i];
    __nv_bfloat16 hi = __float2bfloat16(v);
    __nv_bfloat16 lo = __float2bfloat16(v - __bfloat162float(hi));
    size_t base = (size_t)n * K2EXT;
    g_B2[base + k]            = hi;
    g_B2[base + NHID + k]     = hi;
    g_B2[base + 2 * NHID + k] = lo;
}

// ---------------- HMMA GEMM (mma.sync m16n8k16 bf16) ------------------------
// C[M, NTOT] = A[M, KEXT] @ B[NTOT, KEXT]^T  (A row-major, B n-major/K-contig)
// BM=128, BK=32, 256 threads (8 warps, WARPS_M x WARPS_N).
// smem rows padded to 80 bytes (40 bf16) -> conflict-free ldmatrix.
template<int BN, int KEXT, int WARPS_M, int WARPS_N>
__global__ __launch_bounds__(256) void hmma_gemm_k(const __nv_bfloat16* __restrict__ A,
                                                   const __nv_bfloat16* __restrict__ Bm,
                                                   float* __restrict__ C,
                                                   int M, int NTOT) {
    constexpr int BM = 128, BK = 32;
    constexpr int STRIDE_B = 80;                 // bytes per smem row
    constexpr int A_BUF = BM * STRIDE_B;         // 10240
    constexpr int B_BUF = BN * STRIDE_B;
    constexpr int NC = KEXT / BK;
    constexpr int WT_M = BM / WARPS_M;           // warp tile M
    constexpr int WT_N = BN / WARPS_N;           // warp tile N (=32 both cfgs)
    constexpr int MT = WT_M / 16;
    constexpr int NTT = WT_N / 8;                // 4

    __shared__ char smem[2 * (A_BUF + B_BUF)];
    uint32_t sa = smem_u32(smem);
    uint32_t sbB = sa + 2 * A_BUF;

    int tid = threadIdx.x, warp = tid >> 5, lane = tid & 31;
    int m0 = blockIdx.x * BM;
    int n0 = blockIdx.y * BN;
    int wm = warp % WARPS_M, wn = warp / WARPS_M;
    int wm0 = wm * WT_M, wn0 = wn * WT_N;

    const char* Agl = (const char*)(A + (size_t)m0 * KEXT);
    const char* Bgl = (const char*)(Bm + (size_t)n0 * KEXT);

    auto load_tile = [&](int c, int buf) {
        int koff = c * BK * 2;                   // byte offset along K
        uint32_t ad = sa + buf * A_BUF;
#pragma unroll
        for (int u = 0; u < (BM * 4) / 256; u++) {
            int idx = u * 256 + tid;
            int r = idx >> 2, ch = idx & 3;
            uint32_t dst = ad + r * STRIDE_B + ch * 16;
            const void* src = Agl + (size_t)r * (KEXT * 2) + koff + ch * 16;
            asm volatile("cp.async.cg.shared.global [%0], [%1], 16;"
                         :: "r"(dst), "l"(src));
        }
        uint32_t bd = sbB + buf * B_BUF;
#pragma unroll
        for (int u = 0; u < (BN * 4) / 256; u++) {
            int idx = u * 256 + tid;
            int r = idx >> 2, ch = idx & 3;
            uint32_t dst = bd + r * STRIDE_B + ch * 16;
            const void* src = Bgl + (size_t)r * (KEXT * 2) + koff + ch * 16;
            asm volatile("cp.async.cg.shared.global [%0], [%1], 16;"
                         :: "r"(dst), "l"(src));
        }
        asm volatile("cp.async.commit_group;");
    };

    float acc[MT][NTT][4];
#pragma unroll
    for (int i = 0; i < MT; i++)
#pragma unroll
        for (int j = 0; j < NTT; j++)
#pragma unroll
            for (int q = 0; q < 4; q++) acc[i][j][q] = 0.f;

    load_tile(0, 0);

    for (int c = 0; c < NC; c++) {
        int buf = c & 1;
        if (c + 1 < NC) {
            load_tile(c + 1, buf ^ 1);
            asm volatile("cp.async.wait_group 1;");
        } else {
            asm volatile("cp.async.wait_group 0;");
        }
        __syncthreads();

        uint32_t abase = sa + buf * A_BUF;
        uint32_t bbase = sbB + buf * B_BUF;
#pragma unroll
        for (int kk = 0; kk < 2; kk++) {         // two k16 steps per BK=32
            uint32_t af[MT][4];
#pragma unroll
            for (int mt = 0; mt < MT; mt++) {
                uint32_t addr = abase
                    + (wm0 + mt * 16 + (lane & 15)) * STRIDE_B
                    + kk * 32 + (lane >> 4) * 16;
                asm volatile(
                    "ldmatrix.sync.aligned.m8n8.x4.shared.b16 {%0,%1,%2,%3}, [%4];"
                    : "=r"(af[mt][0]), "=r"(af[mt][1]),
                      "=r"(af[mt][2]), "=r"(af[mt][3])
                    : "r"(addr));
            }
            uint32_t bf[NTT][2];
#pragma unroll
            for (int nb = 0; nb < NTT / 2; nb++) {
                int nrow = wn0 + nb * 16 + (lane & 7) + ((lane >> 4) & 1) * 8;
                int khalf = (lane >> 3) & 1;
                uint32_t addr = bbase + nrow * STRIDE_B + kk * 32 + khalf * 16;
                asm volatile(
                    "ldmatrix.sync.aligned.m8n8.x4.shared.b16 {%0,%1,%2,%3}, [%4];"
                    : "=r"(bf[nb * 2][0]), "=r"(bf[nb * 2][1]),
                      "=r"(bf[nb * 2 + 1][0]), "=r"(bf[nb * 2 + 1][1])
                    : "r"(addr));
            }
#pragma unroll
            for (int mt = 0; mt < MT; mt++)
#pragma unroll
                for (int nt = 0; nt < NTT; nt++) {
                    asm volatile(
                        "mma.sync.aligned.m16n8k16.row.col.f32.bf16.bf16.f32 "
                        "{%0,%1,%2,%3}, {%4,%5,%6,%7}, {%8,%9}, {%0,%1,%2,%3};"
                        : "+f"(acc[mt][nt][0]), "+f"(acc[mt][nt][1]),
                          "+f"(acc[mt][nt][2]), "+f"(acc[mt][nt][3])
                        : "r"(af[mt][0]), "r"(af[mt][1]),
                          "r"(af[mt][2]), "r"(af[mt][3]),
                          "r"(bf[nt][0]), "r"(bf[nt][1]));
                }
        }
        __syncthreads();
    }

    // epilogue: scatter C fragments
#pragma unroll
    for (int mt = 0; mt < MT; mt++) {
        int r0 = m0 + wm0 + mt * 16 + (lane >> 2);
#pragma unroll
        for (int nt = 0; nt < NTT; nt++) {
            int cc = n0 + wn0 + nt * 8 + (lane & 3) * 2;
            if (r0 < M) {
                float2 v = make_float2(acc[mt][nt][0], acc[mt][nt][1]);
                *(float2*)(C + (size_t)r0 * NTOT + cc) = v;
            }
            if (r0 + 8 < M) {
                float2 v = make_float2(acc[mt][nt][2], acc[mt][nt][3]);
                *(float2*)(C + (size_t)(r0 + 8) * NTOT + cc) = v;
            }
        }
    }
}

// ---------------- SpMM layer 1: A2' = split(relu(A @ XW1 + b1)) -------------
__global__ __launch_bounds__(256) void spmm1_k(const float* __restrict__ b1) {
    int node = blockIdx.x;
    int f = threadIdx.x;
    int s = g_row_ptr[node], e = g_row_ptr[node + 1];
    float acc = 0.f;
    for (int i = s; i < e; i++) {
        int   src = __ldg(&g_src_sorted[i]);
        float w   = __ldg(&g_w_sorted[i]);
        acc += w * __ldg(&g_XW1[(size_t)src * NHID + f]);
    }
    float v = fmaxf(acc + b1[f], 0.f);
    __nv_bfloat16 hi = __float2bfloat16(v);
    __nv_bfloat16 lo = __float2bfloat16(v - __bfloat162float(hi));
    size_t base = (size_t)node * K2EXT;
    g_A2[base + f]            = hi;
    g_A2[base + NHID + f]     = lo;
    g_A2[base + 2 * NHID + f] = hi;
}

// ---------------- SpMM layer 2 fused with bias + log_softmax ----------------
__global__ __launch_bounds__(256) void spmm2_lsm_k(const float* __restrict__ b2,
                                                   float* __restrict__ out) {
    int grp  = threadIdx.x >> 6;
    int f    = threadIdx.x & 63;
    int node = blockIdx.x * 4 + grp;

    int s = g_row_ptr[node], e = g_row_ptr[node + 1];
    float acc = 0.f;
    for (int i = s; i < e; i++) {
        int   src = __ldg(&g_src_sorted[i]);
        float w   = __ldg(&g_w_sorted[i]);
        acc += w * __ldg(&g_HW2[(size_t)src * NCLASS + f]);
    }
    float logit = acc + b2[f];

    float m = logit;
#pragma unroll
    for (int o = 16; o > 0; o >>= 1) m = fmaxf(m, __shfl_xor_sync(0xffffffffu, m, o));
    __shared__ float sh_max[8];
    int warp = threadIdx.x >> 5;
    if ((threadIdx.x & 31) == 0) sh_max[warp] = m;
    __syncthreads();
    m = fmaxf(sh_max[grp * 2], sh_max[grp * 2 + 1]);

    float ex = __expf(logit - m);
    float sum = ex;
#pragma unroll
    for (int o = 16; o > 0; o >>= 1) sum += __shfl_xor_sync(0xffffffffu, sum, o);
    __shared__ float sh_sum[8];
    if ((threadIdx.x & 31) == 0) sh_sum[warp] = sum;
    __syncthreads();
    float total = sh_sum[grp * 2] + sh_sum[grp * 2 + 1];

    out[(size_t)node * NCLASS + f] = logit - m - __logf(total);
}

// ---------------- launch ----------------------------------------------------
extern "C" void kernel_launch(void* const* d_in, const int* in_sizes, int n_in,
                              void* d_out, int out_size) {
    const float* x    = (const float*)d_in[0];
    const float* W1   = (const float*)d_in[1];
    const float* b1   = (const float*)d_in[2];
    const float* W2   = (const float*)d_in[3];
    const float* b2   = (const float*)d_in[4];
    const float* ew   = (const float*)d_in[5];
    const int*   esrc = (const int*)d_in[6];
    const int*   edst = (const int*)d_in[7];
    float* out = (float*)d_out;

    __nv_bfloat16 *dA1, *dB1, *dA2, *dB2;
    float *dXW1, *dHW2;
    cudaGetSymbolAddress((void**)&dA1, g_A1);
    cudaGetSymbolAddress((void**)&dB1, g_B1);
    cudaGetSymbolAddress((void**)&dA2, g_A2);
    cudaGetSymbolAddress((void**)&dB2, g_B2);
    cudaGetSymbolAddress((void**)&dXW1, g_XW1);
    cudaGetSymbolAddress((void**)&dHW2, g_HW2);

    // CSR build
    zero_counts_k<<<(N_NODES + 255) / 256, 256>>>();
    hist_k<<<(N_EDGES + 255) / 256, 256>>>(edst);
    scan_k<<<1, 1024>>>();
    scatter_k<<<(N_EDGES + 255) / 256, 256>>>(esrc, edst, ew);

    // fp32 -> bf16-split conversions
    conv_x_k<<<(N_NODES * NFEAT + 255) / 256, 256>>>(x);
    conv_w1_k<<<(NFEAT * NHID + 255) / 256, 256>>>(W1);
    conv_w2_k<<<(NHID * NCLASS + 255) / 256, 256>>>(W2);

    // layer 1: XW1 = x @ W1 via HMMA (BN=128, 2 N-blocks), then fused SpMM
    {
        dim3 grid(M_PAD / 128, NHID / 128);
        hmma_gemm_k<128, K1EXT, 2, 4><<<grid, 256>>>(dA1, dB1, dXW1,
                                                     N_NODES, NHID);
    }
    spmm1_k<<<N_NODES, 256>>>(b1);

    // layer 2: HW2 = H @ W2 via HMMA (BN=64), then fused SpMM + log_softmax
    {
        dim3 grid(M_PAD / 128, 1);
        hmma_gemm_k<64, K2EXT, 4, 2><<<grid, 256>>>(dA2, dB2, dHW2,
                                                    N_NODES, NCLASS);
    }
    spmm2_lsm_k<<<N_NODES / 4, 256>>>(b2, out);
}

// round 4
// speedup vs baseline: 1.8322x; 1.5567x over previous
#include <cuda_runtime.h>
#include <cuda_bf16.h>
#include <cstdint>

#define N_NODES 50000
#define M_PAD   50048      // 391 * 128
#define N_EDGES 800000
#define NFEAT   512
#define NHID    256
#define NCLASS  64
#define K2EXT   (3*NHID)   // 768

// ---------------- scratch (static device globals; no runtime allocation) ----
__device__ __align__(256) __nv_bfloat16 g_B1[(size_t)NHID * 2 * NFEAT]; // [n][hi512|lo512]
__device__ __align__(256) __nv_bfloat16 g_A2[(size_t)M_PAD * K2EXT];    // 77 MB
__device__ __align__(256) __nv_bfloat16 g_B2[(size_t)NCLASS * K2EXT];
__device__ __align__(256) float g_XW1[(size_t)N_NODES * NHID];          // 51 MB
__device__ __align__(256) float g_HW2[(size_t)N_NODES * NCLASS];        // 13 MB
__device__ int   g_counts [N_NODES];
__device__ int   g_row_ptr[N_NODES + 1];
__device__ int   g_cursor [N_NODES];
__device__ int   g_src_sorted[N_EDGES];
__device__ float g_w_sorted  [N_EDGES];

// ---------------- helpers ---------------------------------------------------
__device__ __forceinline__ uint32_t smem_u32(const void* p) {
    uint32_t a;
    asm("{ .reg .u64 t; cvta.to.shared.u64 t, %1; cvt.u32.u64 %0, t; }"
        : "=r"(a) : "l"(p));
    return a;
}
__device__ __forceinline__ uint32_t pack_bf16(__nv_bfloat16 a, __nv_bfloat16 b) {
    __nv_bfloat162 p(a, b);
    return *(uint32_t*)&p;
}

// ---------------- CSR build -------------------------------------------------
__global__ void zero_counts_k() {
    int i = blockIdx.x * blockDim.x + threadIdx.x;
    if (i < N_NODES) g_counts[i] = 0;
}

__global__ void hist_k(const int* __restrict__ edst) {
    int i = blockIdx.x * blockDim.x + threadIdx.x;
    if (i < N_EDGES) atomicAdd(&g_counts[edst[i]], 1);
}

__global__ __launch_bounds__(1024) void scan_k() {
    __shared__ int part[1024];
    const int CH = 49;
    int t = threadIdx.x;
    int begin = t * CH;
    int end = begin + CH; if (end > N_NODES) end = N_NODES;
    int s = 0;
    for (int i = begin; i < end; i++) s += g_counts[i];
    part[t] = s;
    __syncthreads();
    for (int off = 1; off < 1024; off <<= 1) {
        int v = (t >= off) ? part[t - off] : 0;
        __syncthreads();
        part[t] += v;
        __syncthreads();
    }
    int run = (t == 0) ? 0 : part[t - 1];
    for (int i = begin; i < end; i++) {
        g_row_ptr[i] = run;
        g_cursor[i]  = run;
        run += g_counts[i];
    }
    if (t == 1023) g_row_ptr[N_NODES] = part[1023];
}

__global__ void scatter_k(const int* __restrict__ esrc,
                          const int* __restrict__ edst,
                          const float* __restrict__ ew) {
    int i = blockIdx.x * blockDim.x + threadIdx.x;
    if (i < N_EDGES) {
        int d = edst[i];
        int p = atomicAdd(&g_cursor[d], 1);
        g_src_sorted[p] = esrc[i];
        g_w_sorted[p]   = ew[i];
    }
}

// ---------------- weight conversions ----------------------------------------
// B1: [n][0..511]=hi(W1[k][n]), [512..1023]=lo
__global__ void conv_w1_k(const float* __restrict__ W1) {
    int i = blockIdx.x * blockDim.x + threadIdx.x;
    if (i >= NFEAT * NHID) return;
    int k = i / NHID, n = i - k * NHID;
    float v = W1[i];
    __nv_bfloat16 hi = __float2bfloat16(v);
    __nv_bfloat16 lo = __float2bfloat16(v - __bfloat162float(hi));
    size_t base = (size_t)n * (2 * NFEAT);
    g_B1[base + k]         = hi;
    g_B1[base + NFEAT + k] = lo;
}

// B2: [n][hi(768-ext layout: hi|hi|lo)] matching A2 [hi|lo|hi]
__global__ void conv_w2_k(const float* __restrict__ W2) {
    int i = blockIdx.x * blockDim.x + threadIdx.x;
    if (i >= NHID * NCLASS) return;
    int k = i / NCLASS, n = i - k * NCLASS;
    float v = W2[i];
    __nv_bfloat16 hi = __float2bfloat16(v);
    __nv_bfloat16 lo = __float2bfloat16(v - __bfloat162float(hi));
    size_t base = (size_t)n * K2EXT;
    g_B2[base + k]            = hi;
    g_B2[base + NHID + k]     = hi;
    g_B2[base + 2 * NHID + k] = lo;
}

// ---------------- GEMM1 fused: XW1 = x @ W1 (bf16 3-term split on the fly) --
// BM=128, BN=128, 16 chunks of 32 fp32 features. A converted in-kernel.
// smem: A_hi[0,10240) A_lo[10240,20480) B bufs [20480 + buf*20480) {hi,lo}
__global__ __launch_bounds__(256, 2) void gemm1_fused_k(const float* __restrict__ x,
                                                        const __nv_bfloat16* __restrict__ B1,
                                                        float* __restrict__ C) {
    constexpr int STRIDE_B = 80;
    constexpr int NCH = NFEAT / 32;   // 16
    extern __shared__ char smem[];
    uint32_t sa = smem_u32(smem);

    int tid = threadIdx.x, warp = tid >> 5, lane = tid & 31;
    int m0 = blockIdx.x * 128;
    int n0 = blockIdx.y * 128;
    int wm = warp & 1, wn = warp >> 1;          // 2 x 4 warps
    int wm0 = wm * 64, wn0 = wn * 32;

    // A loader mapping: 2 threads per row, each half-row (16 floats)
    int r = tid >> 1, h = tid & 1;
    bool rowok = (m0 + r) < N_NODES;
    const float* xrow = x + (size_t)(m0 + r) * NFEAT + h * 16;

    // B loader mapping: 4 cp.asyncs per thread per chunk
    const char* Bgl = (const char*)B1;

    auto load_B = [&](int c, int buf) {
        uint32_t bb = sa + 20480 + buf * 20480;
#pragma unroll
        for (int u = 0; u < 4; u++) {
            int idx = u * 256 + tid;
            int tile = idx >> 9;              // 0=hi, 1=lo
            int i2 = idx & 511;
            int row = i2 >> 2, q = i2 & 3;
            uint32_t dst = bb + tile * 10240 + row * STRIDE_B + q * 16;
            const void* src = Bgl + (size_t)(n0 + row) * 2048 + tile * 1024
                            + c * 64 + q * 16;
            asm volatile("cp.async.cg.shared.global [%0], [%1], 16;"
                         :: "r"(dst), "l"(src));
        }
        asm volatile("cp.async.commit_group;");
    };

    float4 pf[4];
#pragma unroll
    for (int j = 0; j < 4; j++)
        pf[j] = rowok ? *(const float4*)(xrow + j * 4)
                      : make_float4(0.f, 0.f, 0.f, 0.f);
    load_B(0, 0);

    float acc[4][4][4];
#pragma unroll
    for (int i = 0; i < 4; i++)
#pragma unroll
        for (int j = 0; j < 4; j++)
#pragma unroll
            for (int q = 0; q < 4; q++) acc[i][j][q] = 0.f;

    for (int c = 0; c < NCH; c++) {
        // convert + store A(c) tiles (hi at 0, lo at 10240)
        {
            char* base = smem + r * STRIDE_B + h * 32;
#pragma unroll
            for (int j = 0; j < 4; j++) {
                float4 v = pf[j];
                __nv_bfloat16 h0 = __float2bfloat16(v.x);
                __nv_bfloat16 h1 = __float2bfloat16(v.y);
                __nv_bfloat16 h2 = __float2bfloat16(v.z);
                __nv_bfloat16 h3 = __float2bfloat16(v.w);
                uint2 hv = make_uint2(pack_bf16(h0, h1), pack_bf16(h2, h3));
                *(uint2*)(base + j * 8) = hv;
                __nv_bfloat16 l0 = __float2bfloat16(v.x - __bfloat162float(h0));
                __nv_bfloat16 l1 = __float2bfloat16(v.y - __bfloat162float(h1));
                __nv_bfloat16 l2 = __float2bfloat16(v.z - __bfloat162float(h2));
                __nv_bfloat16 l3 = __float2bfloat16(v.w - __bfloat162float(h3));
                uint2 lv = make_uint2(pack_bf16(l0, l1), pack_bf16(l2, l3));
                *(uint2*)(base + 10240 + j * 8) = lv;
            }
        }
        if (c + 1 < NCH) {
#pragma unroll
            for (int j = 0; j < 4; j++)
                pf[j] = rowok ? *(const float4*)(xrow + (c + 1) * 32 + j * 4)
                              : make_float4(0.f, 0.f, 0.f, 0.f);
            load_B(c + 1, (c + 1) & 1);
            asm volatile("cp.async.wait_group 1;");
        } else {
            asm volatile("cp.async.wait_group 0;");
        }
        __syncthreads();

        uint32_t aH = sa, aL = sa + 10240;
        uint32_t bb = sa + 20480 + (c & 1) * 20480;
        uint32_t bH = bb, bL = bb + 10240;
#pragma unroll
        for (int kk = 0; kk < 2; kk++) {
            uint32_t af[4][4];
            uint32_t bfH[4][2], bfL[4][2];
#pragma unroll
            for (int mt = 0; mt < 4; mt++) {
                uint32_t addr = aH + (wm0 + mt * 16 + (lane & 15)) * STRIDE_B
                              + kk * 32 + (lane >> 4) * 16;
                asm volatile(
                    "ldmatrix.sync.aligned.m8n8.x4.shared.b16 {%0,%1,%2,%3}, [%4];"
                    : "=r"(af[mt][0]), "=r"(af[mt][1]),
                      "=r"(af[mt][2]), "=r"(af[mt][3]) : "r"(addr));
            }
#pragma unroll
            for (int nb = 0; nb < 2; nb++) {
                int nrow = wn0 + nb * 16 + (lane & 7) + ((lane >> 4) & 1) * 8;
                int khalf = (lane >> 3) & 1;
                uint32_t aH2 = bH + nrow * STRIDE_B + kk * 32 + khalf * 16;
                asm volatile(
                    "ldmatrix.sync.aligned.m8n8.x4.shared.b16 {%0,%1,%2,%3}, [%4];"
                    : "=r"(bfH[nb * 2][0]), "=r"(bfH[nb * 2][1]),
                      "=r"(bfH[nb * 2 + 1][0]), "=r"(bfH[nb * 2 + 1][1])
                    : "r"(aH2));
                uint32_t aL2 = bL + nrow * STRIDE_B + kk * 32 + khalf * 16;
                asm volatile(
                    "ldmatrix.sync.aligned.m8n8.x4.shared.b16 {%0,%1,%2,%3}, [%4];"
                    : "=r"(bfL[nb * 2][0]), "=r"(bfL[nb * 2][1]),
                      "=r"(bfL[nb * 2 + 1][0]), "=r"(bfL[nb * 2 + 1][1])
                    : "r"(aL2));
            }
#define MMA(ACC, AF, BF) \
    asm volatile("mma.sync.aligned.m16n8k16.row.col.f32.bf16.bf16.f32 " \
                 "{%0,%1,%2,%3}, {%4,%5,%6,%7}, {%8,%9}, {%0,%1,%2,%3};" \
                 : "+f"(ACC[0]), "+f"(ACC[1]), "+f"(ACC[2]), "+f"(ACC[3]) \
                 : "r"(AF[0]), "r"(AF[1]), "r"(AF[2]), "r"(AF[3]), \
                   "r"(BF[0]), "r"(BF[1]))
            // hi x hi  and  hi x lo
#pragma unroll
            for (int mt = 0; mt < 4; mt++)
#pragma unroll
                for (int nt = 0; nt < 4; nt++) {
                    MMA(acc[mt][nt], af[mt], bfH[nt]);
                    MMA(acc[mt][nt], af[mt], bfL[nt]);
                }
            // lo x hi (reload A frags from lo tile)
#pragma unroll
            for (int mt = 0; mt < 4; mt++) {
                uint32_t addr = aL + (wm0 + mt * 16 + (lane & 15)) * STRIDE_B
                              + kk * 32 + (lane >> 4) * 16;
                asm volatile(
                    "ldmatrix.sync.aligned.m8n8.x4.shared.b16 {%0,%1,%2,%3}, [%4];"
                    : "=r"(af[mt][0]), "=r"(af[mt][1]),
                      "=r"(af[mt][2]), "=r"(af[mt][3]) : "r"(addr));
            }
#pragma unroll
            for (int mt = 0; mt < 4; mt++)
#pragma unroll
                for (int nt = 0; nt < 4; nt++)
                    MMA(acc[mt][nt], af[mt], bfH[nt]);
#undef MMA
        }
        __syncthreads();
    }

    // epilogue
#pragma unroll
    for (int mt = 0; mt < 4; mt++) {
        int r0 = m0 + wm0 + mt * 16 + (lane >> 2);
#pragma unroll
        for (int nt = 0; nt < 4; nt++) {
            int cc = n0 + wn0 + nt * 8 + (lane & 3) * 2;
            if (r0 < N_NODES)
                *(float2*)(C + (size_t)r0 * NHID + cc) =
                    make_float2(acc[mt][nt][0], acc[mt][nt][1]);
            if (r0 + 8 < N_NODES)
                *(float2*)(C + (size_t)(r0 + 8) * NHID + cc) =
                    make_float2(acc[mt][nt][2], acc[mt][nt][3]);
        }
    }
}

// ---------------- HMMA GEMM (generic, for layer 2) --------------------------
template<int BN, int KEXT, int WARPS_M, int WARPS_N>
__global__ __launch_bounds__(256) void hmma_gemm_k(const __nv_bfloat16* __restrict__ A,
                                                   const __nv_bfloat16* __restrict__ Bm,
                                                   float* __restrict__ C,
                                                   int M, int NTOT) {
    constexpr int BM = 128, BK = 32;
    constexpr int STRIDE_B = 80;
    constexpr int A_BUF = BM * STRIDE_B;
    constexpr int B_BUF = BN * STRIDE_B;
    constexpr int NC = KEXT / BK;
    constexpr int WT_M = BM / WARPS_M;
    constexpr int WT_N = BN / WARPS_N;
    constexpr int MT = WT_M / 16;
    constexpr int NTT = WT_N / 8;

    __shared__ char smem[2 * (A_BUF + B_BUF)];
    uint32_t sa = smem_u32(smem);
    uint32_t sbB = sa + 2 * A_BUF;

    int tid = threadIdx.x, warp = tid >> 5, lane = tid & 31;
    int m0 = blockIdx.x * BM;
    int n0 = blockIdx.y * BN;
    int wm = warp % WARPS_M, wn = warp / WARPS_M;
    int wm0 = wm * WT_M, wn0 = wn * WT_N;

    const char* Agl = (const char*)(A + (size_t)m0 * KEXT);
    const char* Bgl = (const char*)(Bm + (size_t)n0 * KEXT);

    auto load_tile = [&](int c, int buf) {
        int koff = c * BK * 2;
        uint32_t ad = sa + buf * A_BUF;
#pragma unroll
        for (int u = 0; u < (BM * 4) / 256; u++) {
            int idx = u * 256 + tid;
            int r = idx >> 2, ch = idx & 3;
            uint32_t dst = ad + r * STRIDE_B + ch * 16;
            const void* src = Agl + (size_t)r * (KEXT * 2) + koff + ch * 16;
            asm volatile("cp.async.cg.shared.global [%0], [%1], 16;"
                         :: "r"(dst), "l"(src));
        }
        uint32_t bd = sbB + buf * B_BUF;
#pragma unroll
        for (int u = 0; u < (BN * 4) / 256; u++) {
            int idx = u * 256 + tid;
            int r = idx >> 2, ch = idx & 3;
            uint32_t dst = bd + r * STRIDE_B + ch * 16;
            const void* src = Bgl + (size_t)r * (KEXT * 2) + koff + ch * 16;
            asm volatile("cp.async.cg.shared.global [%0], [%1], 16;"
                         :: "r"(dst), "l"(src));
        }
        asm volatile("cp.async.commit_group;");
    };

    float acc[MT][NTT][4];
#pragma unroll
    for (int i = 0; i < MT; i++)
#pragma unroll
        for (int j = 0; j < NTT; j++)
#pragma unroll
            for (int q = 0; q < 4; q++) acc[i][j][q] = 0.f;

    load_tile(0, 0);

    for (int c = 0; c < NC; c++) {
        int buf = c & 1;
        if (c + 1 < NC) {
            load_tile(c + 1, buf ^ 1);
            asm volatile("cp.async.wait_group 1;");
        } else {
            asm volatile("cp.async.wait_group 0;");
        }
        __syncthreads();

        uint32_t abase = sa + buf * A_BUF;
        uint32_t bbase = sbB + buf * B_BUF;
#pragma unroll
        for (int kk = 0; kk < 2; kk++) {
            uint32_t af[MT][4];
#pragma unroll
            for (int mt = 0; mt < MT; mt++) {
                uint32_t addr = abase
                    + (wm0 + mt * 16 + (lane & 15)) * STRIDE_B
                    + kk * 32 + (lane >> 4) * 16;
                asm volatile(
                    "ldmatrix.sync.aligned.m8n8.x4.shared.b16 {%0,%1,%2,%3}, [%4];"
                    : "=r"(af[mt][0]), "=r"(af[mt][1]),
                      "=r"(af[mt][2]), "=r"(af[mt][3])
                    : "r"(addr));
            }
            uint32_t bf[NTT][2];
#pragma unroll
            for (int nb = 0; nb < NTT / 2; nb++) {
                int nrow = wn0 + nb * 16 + (lane & 7) + ((lane >> 4) & 1) * 8;
                int khalf = (lane >> 3) & 1;
                uint32_t addr = bbase + nrow * STRIDE_B + kk * 32 + khalf * 16;
                asm volatile(
                    "ldmatrix.sync.aligned.m8n8.x4.shared.b16 {%0,%1,%2,%3}, [%4];"
                    : "=r"(bf[nb * 2][0]), "=r"(bf[nb * 2][1]),
                      "=r"(bf[nb * 2 + 1][0]), "=r"(bf[nb * 2 + 1][1])
                    : "r"(addr));
            }
#pragma unroll
            for (int mt = 0; mt < MT; mt++)
#pragma unroll
                for (int nt = 0; nt < NTT; nt++) {
                    asm volatile(
                        "mma.sync.aligned.m16n8k16.row.col.f32.bf16.bf16.f32 "
                        "{%0,%1,%2,%3}, {%4,%5,%6,%7}, {%8,%9}, {%0,%1,%2,%3};"
                        : "+f"(acc[mt][nt][0]), "+f"(acc[mt][nt][1]),
                          "+f"(acc[mt][nt][2]), "+f"(acc[mt][nt][3])
                        : "r"(af[mt][0]), "r"(af[mt][1]),
                          "r"(af[mt][2]), "r"(af[mt][3]),
                          "r"(bf[nt][0]), "r"(bf[nt][1]));
                }
        }
        __syncthreads();
    }

#pragma unroll
    for (int mt = 0; mt < MT; mt++) {
        int r0 = m0 + wm0 + mt * 16 + (lane >> 2);
#pragma unroll
        for (int nt = 0; nt < NTT; nt++) {
            int cc = n0 + wn0 + nt * 8 + (lane & 3) * 2;
            if (r0 < M)
                *(float2*)(C + (size_t)r0 * NTOT + cc) =
                    make_float2(acc[mt][nt][0], acc[mt][nt][1]);
            if (r0 + 8 < M)
                *(float2*)(C + (size_t)(r0 + 8) * NTOT + cc) =
                    make_float2(acc[mt][nt][2], acc[mt][nt][3]);
        }
    }
}

// ---------------- SpMM layer 1: A2' = split(relu(A @ XW1 + b1)) -------------
__global__ __launch_bounds__(256) void spmm1_k(const float* __restrict__ b1) {
    int node = blockIdx.x;
    int f = threadIdx.x;
    int s = g_row_ptr[node], e = g_row_ptr[node + 1];
    float acc = 0.f;
    for (int i = s; i < e; i++) {
        int   src = __ldg(&g_src_sorted[i]);
        float w   = __ldg(&g_w_sorted[i]);
        acc += w * __ldg(&g_XW1[(size_t)src * NHID + f]);
    }
    float v = fmaxf(acc + b1[f], 0.f);
    __nv_bfloat16 hi = __float2bfloat16(v);
    __nv_bfloat16 lo = __float2bfloat16(v - __bfloat162float(hi));
    size_t base = (size_t)node * K2EXT;
    g_A2[base + f]            = hi;
    g_A2[base + NHID + f]     = lo;
    g_A2[base + 2 * NHID + f] = hi;
}

// ---------------- SpMM layer 2 fused with bias + log_softmax ----------------
__global__ __launch_bounds__(256) void spmm2_lsm_k(const float* __restrict__ b2,
                                                   float* __restrict__ out) {
    int grp  = threadIdx.x >> 6;
    int f    = threadIdx.x & 63;
    int node = blockIdx.x * 4 + grp;

    int s = g_row_ptr[node], e = g_row_ptr[node + 1];
    float acc = 0.f;
    for (int i = s; i < e; i++) {
        int   src = __ldg(&g_src_sorted[i]);
        float w   = __ldg(&g_w_sorted[i]);
        acc += w * __ldg(&g_HW2[(size_t)src * NCLASS + f]);
    }
    float logit = acc + b2[f];

    float m = logit;
#pragma unroll
    for (int o = 16; o > 0; o >>= 1) m = fmaxf(m, __shfl_xor_sync(0xffffffffu, m, o));
    __shared__ float sh_max[8];
    int warp = threadIdx.x >> 5;
    if ((threadIdx.x & 31) == 0) sh_max[warp] = m;
    __syncthreads();
    m = fmaxf(sh_max[grp * 2], sh_max[grp * 2 + 1]);

    float ex = __expf(logit - m);
    float sum = ex;
#pragma unroll
    for (int o = 16; o > 0; o >>= 1) sum += __shfl_xor_sync(0xffffffffu, sum, o);
    __shared__ float sh_sum[8];
    if ((threadIdx.x & 31) == 0) sh_sum[warp] = sum;
    __syncthreads();
    float total = sh_sum[grp * 2] + sh_sum[grp * 2 + 1];

    out[(size_t)node * NCLASS + f] = logit - m - __logf(total);
}

// ---------------- launch ----------------------------------------------------
extern "C" void kernel_launch(void* const* d_in, const int* in_sizes, int n_in,
                              void* d_out, int out_size) {
    const float* x    = (const float*)d_in[0];
    const float* W1   = (const float*)d_in[1];
    const float* b1   = (const float*)d_in[2];
    const float* W2   = (const float*)d_in[3];
    const float* b2   = (const float*)d_in[4];
    const float* ew   = (const float*)d_in[5];
    const int*   esrc = (const int*)d_in[6];
    const int*   edst = (const int*)d_in[7];
    float* out = (float*)d_out;

    __nv_bfloat16 *dB1, *dA2, *dB2;
    float *dXW1, *dHW2;
    cudaGetSymbolAddress((void**)&dB1, g_B1);
    cudaGetSymbolAddress((void**)&dA2, g_A2);
    cudaGetSymbolAddress((void**)&dB2, g_B2);
    cudaGetSymbolAddress((void**)&dXW1, g_XW1);
    cudaGetSymbolAddress((void**)&dHW2, g_HW2);

    const int SMEM_G1 = 20480 + 2 * 20480;   // 61440
    static bool s_init = false;
    static cudaStream_t s_csr;
    static cudaEvent_t ev_root, ev_csr;
    if (!s_init) {
        cudaFuncSetAttribute(gemm1_fused_k,
                             cudaFuncAttributeMaxDynamicSharedMemorySize, SMEM_G1);
        cudaStreamCreateWithFlags(&s_csr, cudaStreamNonBlocking);
        cudaEventCreateWithFlags(&ev_root, cudaEventDisableTiming);
        cudaEventCreateWithFlags(&ev_csr, cudaEventDisableTiming);
        s_init = true;
    }

    // fork: CSR build on side stream (independent of the GEMM chain)
    cudaEventRecord(ev_root, 0);
    cudaStreamWaitEvent(s_csr, ev_root, 0);
    zero_counts_k<<<(N_NODES + 255) / 256, 256, 0, s_csr>>>();
    hist_k<<<(N_EDGES + 255) / 256, 256, 0, s_csr>>>(edst);
    scan_k<<<1, 1024, 0, s_csr>>>();
    scatter_k<<<(N_EDGES + 255) / 256, 256, 0, s_csr>>>(esrc, edst, ew);
    cudaEventRecord(ev_csr, s_csr);

    // main chain: weight conversions + fused GEMM1
    conv_w1_k<<<(NFEAT * NHID + 255) / 256, 256>>>(W1);
    conv_w2_k<<<(NHID * NCLASS + 255) / 256, 256>>>(W2);
    {
        dim3 grid(M_PAD / 128, NHID / 128);
        gemm1_fused_k<<<grid, 256, SMEM_G1>>>(x, dB1, dXW1);
    }

    // join: spmm needs CSR
    cudaStreamWaitEvent(0, ev_csr, 0);
    spmm1_k<<<N_NODES, 256>>>(b1);

    {
        dim3 grid(M_PAD / 128, 1);
        hmma_gemm_k<64, K2EXT, 4, 2><<<grid, 256>>>(dA2, dB2, dHW2,
                                                    N_NODES, NCLASS);
    }
    spmm2_lsm_k<<<N_NODES / 4, 256>>>(b2, out);
}

// round 5
// speedup vs baseline: 2.5170x; 1.3737x over previous
#include <cuda_runtime.h>
#include <cuda_bf16.h>
#include <cstdint>

#define N_NODES 50000
#define M_PAD   50048      // 391 * 128
#define N_EDGES 800000
#define NFEAT   512
#define NHID    256
#define NCLASS  64
#define K2EXT   (3*NHID)   // 768

// ---------------- scratch (static device globals; no runtime allocation) ----
__device__ __align__(256) __nv_bfloat16 g_B1[(size_t)NHID * 2 * NFEAT]; // [n][hi512|lo512]
__device__ __align__(256) __nv_bfloat16 g_A2[(size_t)M_PAD * K2EXT];    // 77 MB
__device__ __align__(256) __nv_bfloat16 g_B2[(size_t)NCLASS * K2EXT];
__device__ __align__(256) float g_XW1[(size_t)N_NODES * NHID];          // 51 MB
__device__ __align__(256) float g_HW2[(size_t)N_NODES * NCLASS];        // 13 MB
__device__ int   g_counts [N_NODES];
__device__ int   g_row_ptr[N_NODES + 1];
__device__ int   g_cursor [N_NODES];
__device__ int   g_src_sorted[N_EDGES];
__device__ float g_w_sorted  [N_EDGES];

// ---------------- helpers ---------------------------------------------------
__device__ __forceinline__ uint32_t smem_u32(const void* p) {
    uint32_t a;
    asm("{ .reg .u64 t; cvta.to.shared.u64 t, %1; cvt.u32.u64 %0, t; }"
        : "=r"(a) : "l"(p));
    return a;
}
__device__ __forceinline__ uint32_t pack_bf16(__nv_bfloat16 a, __nv_bfloat16 b) {
    __nv_bfloat162 p(a, b);
    return *(uint32_t*)&p;
}

// ---------------- CSR build -------------------------------------------------
__global__ void zero_counts_k() {
    int i = blockIdx.x * blockDim.x + threadIdx.x;
    if (i < N_NODES) g_counts[i] = 0;
}

__global__ void hist_k(const int* __restrict__ edst) {
    int i = blockIdx.x * blockDim.x + threadIdx.x;
    if (i < N_EDGES) atomicAdd(&g_counts[edst[i]], 1);
}

__global__ __launch_bounds__(1024) void scan_k() {
    __shared__ int part[1024];
    const int CH = 49;
    int t = threadIdx.x;
    int begin = t * CH;
    int end = begin + CH; if (end > N_NODES) end = N_NODES;
    int s = 0;
    for (int i = begin; i < end; i++) s += g_counts[i];
    part[t] = s;
    __syncthreads();
    for (int off = 1; off < 1024; off <<= 1) {
        int v = (t >= off) ? part[t - off] : 0;
        __syncthreads();
        part[t] += v;
        __syncthreads();
    }
    int run = (t == 0) ? 0 : part[t - 1];
    for (int i = begin; i < end; i++) {
        g_row_ptr[i] = run;
        g_cursor[i]  = run;
        run += g_counts[i];
    }
    if (t == 1023) g_row_ptr[N_NODES] = part[1023];
}

__global__ void scatter_k(const int* __restrict__ esrc,
                          const int* __restrict__ edst,
                          const float* __restrict__ ew) {
    int i = blockIdx.x * blockDim.x + threadIdx.x;
    if (i < N_EDGES) {
        int d = edst[i];
        int p = atomicAdd(&g_cursor[d], 1);
        g_src_sorted[p] = esrc[i];
        g_w_sorted[p]   = ew[i];
    }
}

// ---------------- weight conversions ----------------------------------------
__global__ void conv_w1_k(const float* __restrict__ W1) {
    int i = blockIdx.x * blockDim.x + threadIdx.x;
    if (i >= NFEAT * NHID) return;
    int k = i / NHID, n = i - k * NHID;
    float v = W1[i];
    __nv_bfloat16 hi = __float2bfloat16(v);
    __nv_bfloat16 lo = __float2bfloat16(v - __bfloat162float(hi));
    size_t base = (size_t)n * (2 * NFEAT);
    g_B1[base + k]         = hi;
    g_B1[base + NFEAT + k] = lo;
}

__global__ void conv_w2_k(const float* __restrict__ W2) {
    int i = blockIdx.x * blockDim.x + threadIdx.x;
    if (i >= NHID * NCLASS) return;
    int k = i / NCLASS, n = i - k * NCLASS;
    float v = W2[i];
    __nv_bfloat16 hi = __float2bfloat16(v);
    __nv_bfloat16 lo = __float2bfloat16(v - __bfloat162float(hi));
    size_t base = (size_t)n * K2EXT;
    g_B2[base + k]            = hi;
    g_B2[base + NHID + k]     = hi;
    g_B2[base + 2 * NHID + k] = lo;
}

// ---------------- GEMM1 fused: XW1 = x @ W1, single pass over x -------------
// BM=128, BN=256 (all columns), 512 threads = 16 warps (4x4), warp tile 32x64.
// smem: A_hi[0,10240) A_lo[10240,20480) ; B buf b at 20480+b*40960 {hi,lo}
__global__ __launch_bounds__(512, 1) void gemm1_fused_k(const float* __restrict__ x,
                                                        const __nv_bfloat16* __restrict__ B1,
                                                        float* __restrict__ C) {
    constexpr int STRIDE_B = 80;
    constexpr int NCH = NFEAT / 32;   // 16
    extern __shared__ char smem[];
    uint32_t sa = smem_u32(smem);

    int tid = threadIdx.x, warp = tid >> 5, lane = tid & 31;
    int m0 = blockIdx.x * 128;
    int wm = warp & 3, wn = warp >> 2;          // 4 x 4 warps
    int wm0 = wm * 32, wn0 = wn * 64;

    // A loader: 4 threads per row, 8 floats each
    int r = tid >> 2, q = tid & 3;
    bool rowok = (m0 + r) < N_NODES;
    const float* xrow = x + (size_t)(m0 + r) * NFEAT + q * 8;

    const char* Bgl = (const char*)B1;

    auto load_B = [&](int c, int buf) {
        uint32_t bb = sa + 20480 + buf * 40960;
#pragma unroll
        for (int u = 0; u < 4; u++) {
            int idx = u * 512 + tid;
            int tile = idx >> 10;             // 0=hi, 1=lo
            int i2 = idx & 1023;
            int row = i2 >> 2, qq = i2 & 3;
            uint32_t dst = bb + tile * 20480 + row * STRIDE_B + qq * 16;
            const void* src = Bgl + (size_t)row * 2048 + tile * 1024
                            + c * 64 + qq * 16;
            asm volatile("cp.async.cg.shared.global [%0], [%1], 16;"
                         :: "r"(dst), "l"(src));
        }
        asm volatile("cp.async.commit_group;");
    };

    float4 pf[2];
#pragma unroll
    for (int j = 0; j < 2; j++)
        pf[j] = rowok ? *(const float4*)(xrow + j * 4)
                      : make_float4(0.f, 0.f, 0.f, 0.f);
    load_B(0, 0);

    float acc[2][8][4];
#pragma unroll
    for (int i = 0; i < 2; i++)
#pragma unroll
        for (int j = 0; j < 8; j++)
#pragma unroll
            for (int p = 0; p < 4; p++) acc[i][j][p] = 0.f;

    for (int c = 0; c < NCH; c++) {
        // convert + store A(c) tiles (hi at 0, lo at 10240)
        {
            char* base = smem + r * STRIDE_B + q * 16;
            __nv_bfloat16 h[8], l[8];
#pragma unroll
            for (int j = 0; j < 2; j++) {
                float4 v = pf[j];
                h[j*4+0] = __float2bfloat16(v.x);
                h[j*4+1] = __float2bfloat16(v.y);
                h[j*4+2] = __float2bfloat16(v.z);
                h[j*4+3] = __float2bfloat16(v.w);
                l[j*4+0] = __float2bfloat16(v.x - __bfloat162float(h[j*4+0]));
                l[j*4+1] = __float2bfloat16(v.y - __bfloat162float(h[j*4+1]));
                l[j*4+2] = __float2bfloat16(v.z - __bfloat162float(h[j*4+2]));
                l[j*4+3] = __float2bfloat16(v.w - __bfloat162float(h[j*4+3]));
            }
            uint4 hv = make_uint4(pack_bf16(h[0],h[1]), pack_bf16(h[2],h[3]),
                                  pack_bf16(h[4],h[5]), pack_bf16(h[6],h[7]));
            *(uint4*)base = hv;
            uint4 lv = make_uint4(pack_bf16(l[0],l[1]), pack_bf16(l[2],l[3]),
                                  pack_bf16(l[4],l[5]), pack_bf16(l[6],l[7]));
            *(uint4*)(base + 10240) = lv;
        }
        if (c + 1 < NCH) {
#pragma unroll
            for (int j = 0; j < 2; j++)
                pf[j] = rowok ? *(const float4*)(xrow + (c + 1) * 32 + j * 4)
                              : make_float4(0.f, 0.f, 0.f, 0.f);
            load_B(c + 1, (c + 1) & 1);
            asm volatile("cp.async.wait_group 1;");
        } else {
            asm volatile("cp.async.wait_group 0;");
        }
        __syncthreads();

        uint32_t aH = sa, aL = sa + 10240;
        uint32_t bb = sa + 20480 + (c & 1) * 40960;
        uint32_t bH = bb, bL = bb + 20480;
#pragma unroll
        for (int kk = 0; kk < 2; kk++) {
#pragma unroll
            for (int nh = 0; nh < 2; nh++) {     // two 32-col halves of warp N
                uint32_t af[2][4];
                uint32_t bfH[4][2], bfL[4][2];
#pragma unroll
                for (int mt = 0; mt < 2; mt++) {
                    uint32_t addr = aH + (wm0 + mt * 16 + (lane & 15)) * STRIDE_B
                                  + kk * 32 + (lane >> 4) * 16;
                    asm volatile(
                        "ldmatrix.sync.aligned.m8n8.x4.shared.b16 {%0,%1,%2,%3}, [%4];"
                        : "=r"(af[mt][0]), "=r"(af[mt][1]),
                          "=r"(af[mt][2]), "=r"(af[mt][3]) : "r"(addr));
                }
#pragma unroll
                for (int nb = 0; nb < 2; nb++) {
                    int nrow = wn0 + nh * 32 + nb * 16
                             + (lane & 7) + ((lane >> 4) & 1) * 8;
                    int khalf = (lane >> 3) & 1;
                    uint32_t adH = bH + nrow * STRIDE_B + kk * 32 + khalf * 16;
                    asm volatile(
                        "ldmatrix.sync.aligned.m8n8.x4.shared.b16 {%0,%1,%2,%3}, [%4];"
                        : "=r"(bfH[nb * 2][0]), "=r"(bfH[nb * 2][1]),
                          "=r"(bfH[nb * 2 + 1][0]), "=r"(bfH[nb * 2 + 1][1])
                        : "r"(adH));
                    uint32_t adL = bL + nrow * STRIDE_B + kk * 32 + khalf * 16;
                    asm volatile(
                        "ldmatrix.sync.aligned.m8n8.x4.shared.b16 {%0,%1,%2,%3}, [%4];"
                        : "=r"(bfL[nb * 2][0]), "=r"(bfL[nb * 2][1]),
                          "=r"(bfL[nb * 2 + 1][0]), "=r"(bfL[nb * 2 + 1][1])
                        : "r"(adL));
                }
#define MMA(ACC, AF, BF) \
    asm volatile("mma.sync.aligned.m16n8k16.row.col.f32.bf16.bf16.f32 " \
                 "{%0,%1,%2,%3}, {%4,%5,%6,%7}, {%8,%9}, {%0,%1,%2,%3};" \
                 : "+f"(ACC[0]), "+f"(ACC[1]), "+f"(ACC[2]), "+f"(ACC[3]) \
                 : "r"(AF[0]), "r"(AF[1]), "r"(AF[2]), "r"(AF[3]), \
                   "r"(BF[0]), "r"(BF[1]))
#pragma unroll
                for (int mt = 0; mt < 2; mt++)
#pragma unroll
                    for (int nt = 0; nt < 4; nt++) {
                        MMA(acc[mt][nh * 4 + nt], af[mt], bfH[nt]);
                        MMA(acc[mt][nh * 4 + nt], af[mt], bfL[nt]);
                    }
                // lo x hi (reload A frags from lo tile)
#pragma unroll
                for (int mt = 0; mt < 2; mt++) {
                    uint32_t addr = aL + (wm0 + mt * 16 + (lane & 15)) * STRIDE_B
                                  + kk * 32 + (lane >> 4) * 16;
                    asm volatile(
                        "ldmatrix.sync.aligned.m8n8.x4.shared.b16 {%0,%1,%2,%3}, [%4];"
                        : "=r"(af[mt][0]), "=r"(af[mt][1]),
                          "=r"(af[mt][2]), "=r"(af[mt][3]) : "r"(addr));
                }
#pragma unroll
                for (int mt = 0; mt < 2; mt++)
#pragma unroll
                    for (int nt = 0; nt < 4; nt++)
                        MMA(acc[mt][nh * 4 + nt], af[mt], bfH[nt]);
#undef MMA
            }
        }
        __syncthreads();
    }

    // epilogue
#pragma unroll
    for (int mt = 0; mt < 2; mt++) {
        int r0 = m0 + wm0 + mt * 16 + (lane >> 2);
#pragma unroll
        for (int nt = 0; nt < 8; nt++) {
            int cc = wn0 + nt * 8 + (lane & 3) * 2;
            if (r0 < N_NODES)
                *(float2*)(C + (size_t)r0 * NHID + cc) =
                    make_float2(acc[mt][nt][0], acc[mt][nt][1]);
            if (r0 + 8 < N_NODES)
                *(float2*)(C + (size_t)(r0 + 8) * NHID + cc) =
                    make_float2(acc[mt][nt][2], acc[mt][nt][3]);
        }
    }
}

// ---------------- HMMA GEMM (generic, for layer 2) --------------------------
template<int BN, int KEXT, int WARPS_M, int WARPS_N>
__global__ __launch_bounds__(256) void hmma_gemm_k(const __nv_bfloat16* __restrict__ A,
                                                   const __nv_bfloat16* __restrict__ Bm,
                                                   float* __restrict__ C,
                                                   int M, int NTOT) {
    constexpr int BM = 128, BK = 32;
    constexpr int STRIDE_B = 80;
    constexpr int A_BUF = BM * STRIDE_B;
    constexpr int B_BUF = BN * STRIDE_B;
    constexpr int NC = KEXT / BK;
    constexpr int WT_M = BM / WARPS_M;
    constexpr int WT_N = BN / WARPS_N;
    constexpr int MT = WT_M / 16;
    constexpr int NTT = WT_N / 8;

    __shared__ char smem[2 * (A_BUF + B_BUF)];
    uint32_t sa = smem_u32(smem);
    uint32_t sbB = sa + 2 * A_BUF;

    int tid = threadIdx.x, warp = tid >> 5, lane = tid & 31;
    int m0 = blockIdx.x * BM;
    int n0 = blockIdx.y * BN;
    int wm = warp % WARPS_M, wn = warp / WARPS_M;
    int wm0 = wm * WT_M, wn0 = wn * WT_N;

    const char* Agl = (const char*)(A + (size_t)m0 * KEXT);
    const char* Bgl = (const char*)(Bm + (size_t)n0 * KEXT);

    auto load_tile = [&](int c, int buf) {
        int koff = c * BK * 2;
        uint32_t ad = sa + buf * A_BUF;
#pragma unroll
        for (int u = 0; u < (BM * 4) / 256; u++) {
            int idx = u * 256 + tid;
            int r = idx >> 2, ch = idx & 3;
            uint32_t dst = ad + r * STRIDE_B + ch * 16;
            const void* src = Agl + (size_t)r * (KEXT * 2) + koff + ch * 16;
            asm volatile("cp.async.cg.shared.global [%0], [%1], 16;"
                         :: "r"(dst), "l"(src));
        }
        uint32_t bd = sbB + buf * B_BUF;
#pragma unroll
        for (int u = 0; u < (BN * 4) / 256; u++) {
            int idx = u * 256 + tid;
            int r = idx >> 2, ch = idx & 3;
            uint32_t dst = bd + r * STRIDE_B + ch * 16;
            const void* src = Bgl + (size_t)r * (KEXT * 2) + koff + ch * 16;
            asm volatile("cp.async.cg.shared.global [%0], [%1], 16;"
                         :: "r"(dst), "l"(src));
        }
        asm volatile("cp.async.commit_group;");
    };

    float acc[MT][NTT][4];
#pragma unroll
    for (int i = 0; i < MT; i++)
#pragma unroll
        for (int j = 0; j < NTT; j++)
#pragma unroll
            for (int p = 0; p < 4; p++) acc[i][j][p] = 0.f;

    load_tile(0, 0);

    for (int c = 0; c < NC; c++) {
        int buf = c & 1;
        if (c + 1 < NC) {
            load_tile(c + 1, buf ^ 1);
            asm volatile("cp.async.wait_group 1;");
        } else {
            asm volatile("cp.async.wait_group 0;");
        }
        __syncthreads();

        uint32_t abase = sa + buf * A_BUF;
        uint32_t bbase = sbB + buf * B_BUF;
#pragma unroll
        for (int kk = 0; kk < 2; kk++) {
            uint32_t af[MT][4];
#pragma unroll
            for (int mt = 0; mt < MT; mt++) {
                uint32_t addr = abase
                    + (wm0 + mt * 16 + (lane & 15)) * STRIDE_B
                    + kk * 32 + (lane >> 4) * 16;
                asm volatile(
                    "ldmatrix.sync.aligned.m8n8.x4.shared.b16 {%0,%1,%2,%3}, [%4];"
                    : "=r"(af[mt][0]), "=r"(af[mt][1]),
                      "=r"(af[mt][2]), "=r"(af[mt][3])
                    : "r"(addr));
            }
            uint32_t bf[NTT][2];
#pragma unroll
            for (int nb = 0; nb < NTT / 2; nb++) {
                int nrow = wn0 + nb * 16 + (lane & 7) + ((lane >> 4) & 1) * 8;
                int khalf = (lane >> 3) & 1;
                uint32_t addr = bbase + nrow * STRIDE_B + kk * 32 + khalf * 16;
                asm volatile(
                    "ldmatrix.sync.aligned.m8n8.x4.shared.b16 {%0,%1,%2,%3}, [%4];"
                    : "=r"(bf[nb * 2][0]), "=r"(bf[nb * 2][1]),
                      "=r"(bf[nb * 2 + 1][0]), "=r"(bf[nb * 2 + 1][1])
                    : "r"(addr));
            }
#pragma unroll
            for (int mt = 0; mt < MT; mt++)
#pragma unroll
                for (int nt = 0; nt < NTT; nt++) {
                    asm volatile(
                        "mma.sync.aligned.m16n8k16.row.col.f32.bf16.bf16.f32 "
                        "{%0,%1,%2,%3}, {%4,%5,%6,%7}, {%8,%9}, {%0,%1,%2,%3};"
                        : "+f"(acc[mt][nt][0]), "+f"(acc[mt][nt][1]),
                          "+f"(acc[mt][nt][2]), "+f"(acc[mt][nt][3])
                        : "r"(af[mt][0]), "r"(af[mt][1]),
                          "r"(af[mt][2]), "r"(af[mt][3]),
                          "r"(bf[nt][0]), "r"(bf[nt][1]));
                }
        }
        __syncthreads();
    }

#pragma unroll
    for (int mt = 0; mt < MT; mt++) {
        int r0 = m0 + wm0 + mt * 16 + (lane >> 2);
#pragma unroll
        for (int nt = 0; nt < NTT; nt++) {
            int cc = n0 + wn0 + nt * 8 + (lane & 3) * 2;
            if (r0 < M)
                *(float2*)(C + (size_t)r0 * NTOT + cc) =
                    make_float2(acc[mt][nt][0], acc[mt][nt][1]);
            if (r0 + 8 < M)
                *(float2*)(C + (size_t)(r0 + 8) * NTOT + cc) =
                    make_float2(acc[mt][nt][2], acc[mt][nt][3]);
        }
    }
}

// ---------------- SpMM layer 1: A2' = split(relu(A @ XW1 + b1)) -------------
// 4 nodes per 256-thread block; 64 threads per node, float4 per thread.
__global__ __launch_bounds__(256) void spmm1_k(const float* __restrict__ b1) {
    int t = threadIdx.x;
    int node = blockIdx.x * 4 + (t >> 6);
    int fb = (t & 63) * 4;
    int s = g_row_ptr[node], e = g_row_ptr[node + 1];

    float4 acc = make_float4(0.f, 0.f, 0.f, 0.f);
    int i = s;
    for (; i + 2 <= e; i += 2) {
        int   s0 = __ldg(&g_src_sorted[i]);
        int   s1 = __ldg(&g_src_sorted[i + 1]);
        float w0 = __ldg(&g_w_sorted[i]);
        float w1 = __ldg(&g_w_sorted[i + 1]);
        float4 v0 = __ldg((const float4*)(g_XW1 + (size_t)s0 * NHID + fb));
        float4 v1 = __ldg((const float4*)(g_XW1 + (size_t)s1 * NHID + fb));
        acc.x += w0 * v0.x; acc.y += w0 * v0.y;
        acc.z += w0 * v0.z; acc.w += w0 * v0.w;
        acc.x += w1 * v1.x; acc.y += w1 * v1.y;
        acc.z += w1 * v1.z; acc.w += w1 * v1.w;
    }
    if (i < e) {
        int   s0 = __ldg(&g_src_sorted[i]);
        float w0 = __ldg(&g_w_sorted[i]);
        float4 v0 = __ldg((const float4*)(g_XW1 + (size_t)s0 * NHID + fb));
        acc.x += w0 * v0.x; acc.y += w0 * v0.y;
        acc.z += w0 * v0.z; acc.w += w0 * v0.w;
    }
    float4 bb = __ldg((const float4*)(b1 + fb));
    float v0 = fmaxf(acc.x + bb.x, 0.f);
    float v1 = fmaxf(acc.y + bb.y, 0.f);
    float v2 = fmaxf(acc.z + bb.z, 0.f);
    float v3 = fmaxf(acc.w + bb.w, 0.f);

    __nv_bfloat16 h0 = __float2bfloat16(v0), h1 = __float2bfloat16(v1);
    __nv_bfloat16 h2 = __float2bfloat16(v2), h3 = __float2bfloat16(v3);
    uint2 hv = make_uint2(pack_bf16(h0, h1), pack_bf16(h2, h3));
    __nv_bfloat16 l0 = __float2bfloat16(v0 - __bfloat162float(h0));
    __nv_bfloat16 l1 = __float2bfloat16(v1 - __bfloat162float(h1));
    __nv_bfloat16 l2 = __float2bfloat16(v2 - __bfloat162float(h2));
    __nv_bfloat16 l3 = __float2bfloat16(v3 - __bfloat162float(h3));
    uint2 lv = make_uint2(pack_bf16(l0, l1), pack_bf16(l2, l3));

    size_t base = (size_t)node * K2EXT;
    *(uint2*)(g_A2 + base + fb)            = hv;
    *(uint2*)(g_A2 + base + NHID + fb)     = lv;
    *(uint2*)(g_A2 + base + 2 * NHID + fb) = hv;
}

// ---------------- SpMM layer 2 fused with bias + log_softmax ----------------
// 16 nodes per 256-thread block; 16 threads per node, float4 per thread.
__global__ __launch_bounds__(256) void spmm2_lsm_k(const float* __restrict__ b2,
                                                   float* __restrict__ out) {
    int t = threadIdx.x;
    int node = blockIdx.x * 16 + (t >> 4);
    int fb = (t & 15) * 4;
    int s = g_row_ptr[node], e = g_row_ptr[node + 1];

    float4 acc = make_float4(0.f, 0.f, 0.f, 0.f);
    int i = s;
    for (; i + 2 <= e; i += 2) {
        int   s0 = __ldg(&g_src_sorted[i]);
        int   s1 = __ldg(&g_src_sorted[i + 1]);
        float w0 = __ldg(&g_w_sorted[i]);
        float w1 = __ldg(&g_w_sorted[i + 1]);
        float4 v0 = __ldg((const float4*)(g_HW2 + (size_t)s0 * NCLASS + fb));
        float4 v1 = __ldg((const float4*)(g_HW2 + (size_t)s1 * NCLASS + fb));
        acc.x += w0 * v0.x; acc.y += w0 * v0.y;
        acc.z += w0 * v0.z; acc.w += w0 * v0.w;
        acc.x += w1 * v1.x; acc.y += w1 * v1.y;
        acc.z += w1 * v1.z; acc.w += w1 * v1.w;
    }
    if (i < e) {
        int   s0 = __ldg(&g_src_sorted[i]);
        float w0 = __ldg(&g_w_sorted[i]);
        float4 v0 = __ldg((const float4*)(g_HW2 + (size_t)s0 * NCLASS + fb));
        acc.x += w0 * v0.x; acc.y += w0 * v0.y;
        acc.z += w0 * v0.z; acc.w += w0 * v0.w;
    }
    float4 bb = __ldg((const float4*)(b2 + fb));
    float4 lg = make_float4(acc.x + bb.x, acc.y + bb.y,
                            acc.z + bb.z, acc.w + bb.w);

    float m = fmaxf(fmaxf(lg.x, lg.y), fmaxf(lg.z, lg.w));
#pragma unroll
    for (int o = 8; o > 0; o >>= 1)
        m = fmaxf(m, __shfl_xor_sync(0xffffffffu, m, o));

    float ex = __expf(lg.x - m) + __expf(lg.y - m)
             + __expf(lg.z - m) + __expf(lg.w - m);
#pragma unroll
    for (int o = 8; o > 0; o >>= 1)
        ex += __shfl_xor_sync(0xffffffffu, ex, o);

    float lz = m + __logf(ex);
    float4 r = make_float4(lg.x - lz, lg.y - lz, lg.z - lz, lg.w - lz);
    *(float4*)(out + (size_t)node * NCLASS + fb) = r;
}

// ---------------- launch ----------------------------------------------------
extern "C" void kernel_launch(void* const* d_in, const int* in_sizes, int n_in,
                              void* d_out, int out_size) {
    const float* x    = (const float*)d_in[0];
    const float* W1   = (const float*)d_in[1];
    const float* b1   = (const float*)d_in[2];
    const float* W2   = (const float*)d_in[3];
    const float* b2   = (const float*)d_in[4];
    const float* ew   = (const float*)d_in[5];
    const int*   esrc = (const int*)d_in[6];
    const int*   edst = (const int*)d_in[7];
    float* out = (float*)d_out;

    __nv_bfloat16 *dB1, *dA2, *dB2;
    float *dXW1, *dHW2;
    cudaGetSymbolAddress((void**)&dB1, g_B1);
    cudaGetSymbolAddress((void**)&dA2, g_A2);
    cudaGetSymbolAddress((void**)&dB2, g_B2);
    cudaGetSymbolAddress((void**)&dXW1, g_XW1);
    cudaGetSymbolAddress((void**)&dHW2, g_HW2);

    const int SMEM_G1 = 20480 + 2 * 40960;   // 102400
    static bool s_init = false;
    static cudaStream_t s_csr;
    static cudaEvent_t ev_root, ev_csr;
    if (!s_init) {
        cudaFuncSetAttribute(gemm1_fused_k,
                             cudaFuncAttributeMaxDynamicSharedMemorySize, SMEM_G1);
        cudaStreamCreateWithFlags(&s_csr, cudaStreamNonBlocking);
        cudaEventCreateWithFlags(&ev_root, cudaEventDisableTiming);
        cudaEventCreateWithFlags(&ev_csr, cudaEventDisableTiming);
        s_init = true;
    }

    // fork: CSR build on side stream (independent of the GEMM chain)
    cudaEventRecord(ev_root, 0);
    cudaStreamWaitEvent(s_csr, ev_root, 0);
    zero_counts_k<<<(N_NODES + 255) / 256, 256, 0, s_csr>>>();
    hist_k<<<(N_EDGES + 255) / 256, 256, 0, s_csr>>>(edst);
    scan_k<<<1, 1024, 0, s_csr>>>();
    scatter_k<<<(N_EDGES + 255) / 256, 256, 0, s_csr>>>(esrc, edst, ew);
    cudaEventRecord(ev_csr, s_csr);

    // main chain: weight conversions + fused GEMM1 (single pass over x)
    conv_w1_k<<<(NFEAT * NHID + 255) / 256, 256>>>(W1);
    conv_w2_k<<<(NHID * NCLASS + 255) / 256, 256>>>(W2);
    gemm1_fused_k<<<M_PAD / 128, 512, SMEM_G1>>>(x, dB1, dXW1);

    // join: spmm needs CSR
    cudaStreamWaitEvent(0, ev_csr, 0);
    spmm1_k<<<N_NODES / 4, 256>>>(b1);

    {
        dim3 grid(M_PAD / 128, 1);
        hmma_gemm_k<64, K2EXT, 4, 2><<<grid, 256>>>(dA2, dB2, dHW2,
                                                    N_NODES, NCLASS);
    }
    spmm2_lsm_k<<<N_NODES / 16, 256>>>(b2, out);
}

// round 7
// speedup vs baseline: 3.1558x; 1.2538x over previous
#include <cuda_runtime.h>
#include <cuda_fp16.h>
#include <cstdint>

#define N_NODES 50000
#define M_PAD   50048      // 391 * 128
#define N_EDGES 800000
#define NFEAT   512
#define NHID    256
#define NCLASS  64
#define K2EXT   512        // [h_hi 256 | h_lo 256]

// ---------------- scratch (static device globals; no runtime allocation) ----
__device__ __align__(256) __half g_B1[(size_t)NHID * NFEAT];     // [n][k] = fp16(W1[k][n])
__device__ __align__(256) __half g_A2[(size_t)M_PAD * K2EXT];    // 51 MB
__device__ __align__(256) __half g_B2[(size_t)NCLASS * K2EXT];   // [n][hi256|hi256]
__device__ __align__(256) __half g_XW1[(size_t)N_NODES * NHID];  // 26 MB
__device__ __align__(256) __half g_HW2[(size_t)N_NODES * NCLASS];// 6.4 MB
__device__ int   g_counts [N_NODES];
__device__ int   g_row_ptr[N_NODES + 1];
__device__ int   g_cursor [N_NODES];
__device__ int   g_src_sorted[N_EDGES];
__device__ float g_w_sorted  [N_EDGES];

// ---------------- helpers ---------------------------------------------------
__device__ __forceinline__ uint32_t smem_u32(const void* p) {
    uint32_t a;
    asm("{ .reg .u64 t; cvta.to.shared.u64 t, %1; cvt.u32.u64 %0, t; }"
        : "=r"(a) : "l"(p));
    return a;
}
__device__ __forceinline__ uint32_t pack_h2(__half a, __half b) {
    __half2 p(a, b);
    return *(uint32_t*)&p;
}

// ---------------- CSR build -------------------------------------------------
__global__ void zero_counts_k() {
    int i = blockIdx.x * blockDim.x + threadIdx.x;
    if (i < N_NODES) g_counts[i] = 0;
}

__global__ void hist_k(const int* __restrict__ edst) {
    int i = blockIdx.x * blockDim.x + threadIdx.x;
    if (i < N_EDGES) atomicAdd(&g_counts[edst[i]], 1);
}

__global__ __launch_bounds__(1024) void scan_k() {
    __shared__ int part[1024];
    const int CH = 49;
    int t = threadIdx.x;
    int begin = t * CH;
    int end = begin + CH; if (end > N_NODES) end = N_NODES;
    int s = 0;
    for (int i = begin; i < end; i++) s += g_counts[i];
    part[t] = s;
    __syncthreads();
    for (int off = 1; off < 1024; off <<= 1) {
        int v = (t >= off) ? part[t - off] : 0;
        __syncthreads();
        part[t] += v;
        __syncthreads();
    }
    int run = (t == 0) ? 0 : part[t - 1];
    for (int i = begin; i < end; i++) {
        g_row_ptr[i] = run;
        g_cursor[i]  = run;
        run += g_counts[i];
    }
    if (t == 1023) g_row_ptr[N_NODES] = part[1023];
}

__global__ void scatter_k(const int* __restrict__ esrc,
                          const int* __restrict__ edst,
                          const float* __restrict__ ew) {
    int i = blockIdx.x * blockDim.x + threadIdx.x;
    if (i < N_EDGES) {
        int d = edst[i];
        int p = atomicAdd(&g_cursor[d], 1);
        g_src_sorted[p] = esrc[i];
        g_w_sorted[p]   = ew[i];
    }
}

// ---------------- weight conversions ----------------------------------------
__global__ void conv_w1_k(const float* __restrict__ W1) {
    int i = blockIdx.x * blockDim.x + threadIdx.x;
    if (i >= NFEAT * NHID) return;
    int k = i / NHID, n = i - k * NHID;
    g_B1[(size_t)n * NFEAT + k] = __float2half(W1[i]);
}

__global__ void conv_w2_k(const float* __restrict__ W2) {
    int i = blockIdx.x * blockDim.x + threadIdx.x;
    if (i >= NHID * NCLASS) return;
    int k = i / NCLASS, n = i - k * NCLASS;
    __half hi = __float2half(W2[i]);
    size_t base = (size_t)n * K2EXT;
    g_B2[base + k]        = hi;   // pairs with h_hi
    g_B2[base + NHID + k] = hi;   // pairs with h_lo
}

// ---------------- GEMM1 fused: XW1 = x @ W1, fp16 2-term split --------------
// BM=128, BN=256 (all columns), 512 threads = 16 warps (4x4), warp tile 32x64.
// smem: A_hi[0,10240) A_lo[10240,20480) ; B buf b at 20480+b*20480 (hi only)
__global__ __launch_bounds__(512, 1) void gemm1_fused_k(const float* __restrict__ x,
                                                        const __half* __restrict__ B1,
                                                        __half* __restrict__ C) {
    constexpr int STRIDE_B = 80;
    constexpr int NCH = NFEAT / 32;   // 16
    extern __shared__ char smem[];
    uint32_t sa = smem_u32(smem);

    int tid = threadIdx.x, warp = tid >> 5, lane = tid & 31;
    int m0 = blockIdx.x * 128;
    int wm = warp & 3, wn = warp >> 2;          // 4 x 4 warps
    int wm0 = wm * 32, wn0 = wn * 64;

    // A loader: 4 threads per row, 8 floats each
    int r = tid >> 2, q = tid & 3;
    bool rowok = (m0 + r) < N_NODES;
    const float* xrow = x + (size_t)(m0 + r) * NFEAT + q * 8;

    const char* Bgl = (const char*)B1;

    auto load_B = [&](int c, int buf) {
        uint32_t bb = sa + 20480 + buf * 20480;
#pragma unroll
        for (int u = 0; u < 2; u++) {
            int idx = u * 512 + tid;
            int row = idx >> 2, qq = idx & 3;
            uint32_t dst = bb + row * STRIDE_B + qq * 16;
            const void* src = Bgl + (size_t)row * 1024 + c * 64 + qq * 16;
            asm volatile("cp.async.cg.shared.global [%0], [%1], 16;"
                         :: "r"(dst), "l"(src));
        }
        asm volatile("cp.async.commit_group;");
    };

    float4 pf[2];
#pragma unroll
    for (int j = 0; j < 2; j++)
        pf[j] = rowok ? *(const float4*)(xrow + j * 4)
                      : make_float4(0.f, 0.f, 0.f, 0.f);
    load_B(0, 0);

    float acc[2][8][4];
#pragma unroll
    for (int i = 0; i < 2; i++)
#pragma unroll
        for (int j = 0; j < 8; j++)
#pragma unroll
            for (int p = 0; p < 4; p++) acc[i][j][p] = 0.f;

    for (int c = 0; c < NCH; c++) {
        // convert + store A(c) tiles (hi at 0, lo at 10240)
        {
            char* base = smem + r * STRIDE_B + q * 16;
            __half h[8], l[8];
#pragma unroll
            for (int j = 0; j < 2; j++) {
                float4 v = pf[j];
                h[j*4+0] = __float2half(v.x);
                h[j*4+1] = __float2half(v.y);
                h[j*4+2] = __float2half(v.z);
                h[j*4+3] = __float2half(v.w);
                l[j*4+0] = __float2half(v.x - __half2float(h[j*4+0]));
                l[j*4+1] = __float2half(v.y - __half2float(h[j*4+1]));
                l[j*4+2] = __float2half(v.z - __half2float(h[j*4+2]));
                l[j*4+3] = __float2half(v.w - __half2float(h[j*4+3]));
            }
            uint4 hv = make_uint4(pack_h2(h[0],h[1]), pack_h2(h[2],h[3]),
                                  pack_h2(h[4],h[5]), pack_h2(h[6],h[7]));
            *(uint4*)base = hv;
            uint4 lv = make_uint4(pack_h2(l[0],l[1]), pack_h2(l[2],l[3]),
                                  pack_h2(l[4],l[5]), pack_h2(l[6],l[7]));
            *(uint4*)(base + 10240) = lv;
        }
        if (c + 1 < NCH) {
#pragma unroll
            for (int j = 0; j < 2; j++)
                pf[j] = rowok ? *(const float4*)(xrow + (c + 1) * 32 + j * 4)
                              : make_float4(0.f, 0.f, 0.f, 0.f);
            load_B(c + 1, (c + 1) & 1);
            asm volatile("cp.async.wait_group 1;");
        } else {
            asm volatile("cp.async.wait_group 0;");
        }
        __syncthreads();

        uint32_t aH = sa, aL = sa + 10240;
        uint32_t bH = sa + 20480 + (c & 1) * 20480;
#pragma unroll
        for (int kk = 0; kk < 2; kk++) {
#pragma unroll
            for (int nh = 0; nh < 2; nh++) {     // two 32-col halves of warp N
                uint32_t af[2][4];
                uint32_t bf[4][2];
#pragma unroll
                for (int mt = 0; mt < 2; mt++) {
                    uint32_t addr = aH + (wm0 + mt * 16 + (lane & 15)) * STRIDE_B
                                  + kk * 32 + (lane >> 4) * 16;
                    asm volatile(
                        "ldmatrix.sync.aligned.m8n8.x4.shared.b16 {%0,%1,%2,%3}, [%4];"
                        : "=r"(af[mt][0]), "=r"(af[mt][1]),
                          "=r"(af[mt][2]), "=r"(af[mt][3]) : "r"(addr));
                }
#pragma unroll
                for (int nb = 0; nb < 2; nb++) {
                    int nrow = wn0 + nh * 32 + nb * 16
                             + (lane & 7) + ((lane >> 4) & 1) * 8;
                    int khalf = (lane >> 3) & 1;
                    uint32_t adH = bH + nrow * STRIDE_B + kk * 32 + khalf * 16;
                    asm volatile(
                        "ldmatrix.sync.aligned.m8n8.x4.shared.b16 {%0,%1,%2,%3}, [%4];"
                        : "=r"(bf[nb * 2][0]), "=r"(bf[nb * 2][1]),
                          "=r"(bf[nb * 2 + 1][0]), "=r"(bf[nb * 2 + 1][1])
                        : "r"(adH));
                }
#define MMA(ACC, AF, BF) \
    asm volatile("mma.sync.aligned.m16n8k16.row.col.f32.f16.f16.f32 " \
                 "{%0,%1,%2,%3}, {%4,%5,%6,%7}, {%8,%9}, {%0,%1,%2,%3};" \
                 : "+f"(ACC[0]), "+f"(ACC[1]), "+f"(ACC[2]), "+f"(ACC[3]) \
                 : "r"(AF[0]), "r"(AF[1]), "r"(AF[2]), "r"(AF[3]), \
                   "r"(BF[0]), "r"(BF[1]))
#pragma unroll
                for (int mt = 0; mt < 2; mt++)
#pragma unroll
                    for (int nt = 0; nt < 4; nt++)
                        MMA(acc[mt][nh * 4 + nt], af[mt], bf[nt]);
                // lo_x * hi_w (reload A frags from lo tile)
#pragma unroll
                for (int mt = 0; mt < 2; mt++) {
                    uint32_t addr = aL + (wm0 + mt * 16 + (lane & 15)) * STRIDE_B
                                  + kk * 32 + (lane >> 4) * 16;
                    asm volatile(
                        "ldmatrix.sync.aligned.m8n8.x4.shared.b16 {%0,%1,%2,%3}, [%4];"
                        : "=r"(af[mt][0]), "=r"(af[mt][1]),
                          "=r"(af[mt][2]), "=r"(af[mt][3]) : "r"(addr));
                }
#pragma unroll
                for (int mt = 0; mt < 2; mt++)
#pragma unroll
                    for (int nt = 0; nt < 4; nt++)
                        MMA(acc[mt][nh * 4 + nt], af[mt], bf[nt]);
#undef MMA
            }
        }
        __syncthreads();
    }

    // epilogue: fp16 output
#pragma unroll
    for (int mt = 0; mt < 2; mt++) {
        int r0 = m0 + wm0 + mt * 16 + (lane >> 2);
#pragma unroll
        for (int nt = 0; nt < 8; nt++) {
            int cc = wn0 + nt * 8 + (lane & 3) * 2;
            if (r0 < N_NODES)
                *(uint32_t*)(C + (size_t)r0 * NHID + cc) =
                    pack_h2(__float2half(acc[mt][nt][0]),
                            __float2half(acc[mt][nt][1]));
            if (r0 + 8 < N_NODES)
                *(uint32_t*)(C + (size_t)(r0 + 8) * NHID + cc) =
                    pack_h2(__float2half(acc[mt][nt][2]),
                            __float2half(acc[mt][nt][3]));
        }
    }
}

// ---------------- GEMM2: HW2 = A2 @ B2^T (fp16, K=512, BN=64) --------------
__global__ __launch_bounds__(256) void gemm2_k(const __half* __restrict__ A,
                                               const __half* __restrict__ Bm,
                                               __half* __restrict__ C) {
    constexpr int BM = 128, BN = 64, BK = 32;
    constexpr int STRIDE_B = 80;
    constexpr int A_BUF = BM * STRIDE_B;   // 10240
    constexpr int B_BUF = BN * STRIDE_B;   // 5120
    constexpr int NC = K2EXT / BK;         // 16

    __shared__ char smem[2 * (A_BUF + B_BUF)];
    uint32_t sa = smem_u32(smem);
    uint32_t sbB = sa + 2 * A_BUF;

    int tid = threadIdx.x, warp = tid >> 5, lane = tid & 31;
    int m0 = blockIdx.x * BM;
    int wm = warp & 3, wn = warp >> 2;     // 4 x 2
    int wm0 = wm * 32, wn0 = wn * 32;

    const char* Agl = (const char*)(A + (size_t)m0 * K2EXT);
    const char* Bgl = (const char*)Bm;

    auto load_tile = [&](int c, int buf) {
        int koff = c * BK * 2;
        uint32_t ad = sa + buf * A_BUF;
#pragma unroll
        for (int u = 0; u < 2; u++) {
            int idx = u * 256 + tid;
            int r = idx >> 2, ch = idx & 3;
            uint32_t dst = ad + r * STRIDE_B + ch * 16;
            const void* src = Agl + (size_t)r * (K2EXT * 2) + koff + ch * 16;
            asm volatile("cp.async.cg.shared.global [%0], [%1], 16;"
                         :: "r"(dst), "l"(src));
        }
        uint32_t bd = sbB + buf * B_BUF;
        {
            int r = tid >> 2, ch = tid & 3;
            if (r < BN) {
                uint32_t dst = bd + r * STRIDE_B + ch * 16;
                const void* src = Bgl + (size_t)r * (K2EXT * 2) + koff + ch * 16;
                asm volatile("cp.async.cg.shared.global [%0], [%1], 16;"
                             :: "r"(dst), "l"(src));
            }
        }
        asm volatile("cp.async.commit_group;");
    };

    float acc[2][4][4];
#pragma unroll
    for (int i = 0; i < 2; i++)
#pragma unroll
        for (int j = 0; j < 4; j++)
#pragma unroll
            for (int p = 0; p < 4; p++) acc[i][j][p] = 0.f;

    load_tile(0, 0);

    for (int c = 0; c < NC; c++) {
        int buf = c & 1;
        if (c + 1 < NC) {
            load_tile(c + 1, buf ^ 1);
            asm volatile("cp.async.wait_group 1;");
        } else {
            asm volatile("cp.async.wait_group 0;");
        }
        __syncthreads();

        uint32_t abase = sa + buf * A_BUF;
        uint32_t bbase = sbB + buf * B_BUF;
#pragma unroll
        for (int kk = 0; kk < 2; kk++) {
            uint32_t af[2][4];
#pragma unroll
            for (int mt = 0; mt < 2; mt++) {
                uint32_t addr = abase
                    + (wm0 + mt * 16 + (lane & 15)) * STRIDE_B
                    + kk * 32 + (lane >> 4) * 16;
                asm volatile(
                    "ldmatrix.sync.aligned.m8n8.x4.shared.b16 {%0,%1,%2,%3}, [%4];"
                    : "=r"(af[mt][0]), "=r"(af[mt][1]),
                      "=r"(af[mt][2]), "=r"(af[mt][3])
                    : "r"(addr));
            }
            uint32_t bf[4][2];
#pragma unroll
            for (int nb = 0; nb < 2; nb++) {
                int nrow = wn0 + nb * 16 + (lane & 7) + ((lane >> 4) & 1) * 8;
                int khalf = (lane >> 3) & 1;
                uint32_t addr = bbase + nrow * STRIDE_B + kk * 32 + khalf * 16;
                asm volatile(
                    "ldmatrix.sync.aligned.m8n8.x4.shared.b16 {%0,%1,%2,%3}, [%4];"
                    : "=r"(bf[nb * 2][0]), "=r"(bf[nb * 2][1]),
                      "=r"(bf[nb * 2 + 1][0]), "=r"(bf[nb * 2 + 1][1])
                    : "r"(addr));
            }
#pragma unroll
            for (int mt = 0; mt < 2; mt++)
#pragma unroll
                for (int nt = 0; nt < 4; nt++) {
                    asm volatile(
                        "mma.sync.aligned.m16n8k16.row.col.f32.f16.f16.f32 "
                        "{%0,%1,%2,%3}, {%4,%5,%6,%7}, {%8,%9}, {%0,%1,%2,%3};"
                        : "+f"(acc[mt][nt][0]), "+f"(acc[mt][nt][1]),
                          "+f"(acc[mt][nt][2]), "+f"(acc[mt][nt][3])
                        : "r"(af[mt][0]), "r"(af[mt][1]),
                          "r"(af[mt][2]), "r"(af[mt][3]),
                          "r"(bf[nt][0]), "r"(bf[nt][1]));
                }
        }
        __syncthreads();
    }

#pragma unroll
    for (int mt = 0; mt < 2; mt++) {
        int r0 = m0 + wm0 + mt * 16 + (lane >> 2);
#pragma unroll
        for (int nt = 0; nt < 4; nt++) {
            int cc = wn0 + nt * 8 + (lane & 3) * 2;
            if (r0 < N_NODES)
                *(uint32_t*)(C + (size_t)r0 * NCLASS + cc) =
                    pack_h2(__float2half(acc[mt][nt][0]),
                            __float2half(acc[mt][nt][1]));
            if (r0 + 8 < N_NODES)
                *(uint32_t*)(C + (size_t)(r0 + 8) * NCLASS + cc) =
                    pack_h2(__float2half(acc[mt][nt][2]),
                            __float2half(acc[mt][nt][3]));
        }
    }
}

// ---------------- SpMM layer 1: A2 = split(relu(A @ XW1 + b1)) --------------
// 4 nodes per 256-thread block; 64 threads per node, 4 fp16 feats per thread.
__global__ __launch_bounds__(256) void spmm1_k(const float* __restrict__ b1) {
    int t = threadIdx.x;
    int node = blockIdx.x * 4 + (t >> 6);
    int fb = (t & 63) * 4;
    int s = g_row_ptr[node], e = g_row_ptr[node + 1];

    float a0 = 0.f, a1 = 0.f, a2 = 0.f, a3 = 0.f;
    int i = s;
    for (; i + 2 <= e; i += 2) {
        int   s0 = __ldg(&g_src_sorted[i]);
        int   s1 = __ldg(&g_src_sorted[i + 1]);
        float w0 = __ldg(&g_w_sorted[i]);
        float w1 = __ldg(&g_w_sorted[i + 1]);
        uint2 u0 = __ldg((const uint2*)(g_XW1 + (size_t)s0 * NHID + fb));
        uint2 u1 = __ldg((const uint2*)(g_XW1 + (size_t)s1 * NHID + fb));
        float2 p0 = __half22float2(*(__half2*)&u0.x);
        float2 p1 = __half22float2(*(__half2*)&u0.y);
        a0 += w0 * p0.x; a1 += w0 * p0.y; a2 += w0 * p1.x; a3 += w0 * p1.y;
        float2 q0 = __half22float2(*(__half2*)&u1.x);
        float2 q1 = __half22float2(*(__half2*)&u1.y);
        a0 += w1 * q0.x; a1 += w1 * q0.y; a2 += w1 * q1.x; a3 += w1 * q1.y;
    }
    if (i < e) {
        int   s0 = __ldg(&g_src_sorted[i]);
        float w0 = __ldg(&g_w_sorted[i]);
        uint2 u0 = __ldg((const uint2*)(g_XW1 + (size_t)s0 * NHID + fb));
        float2 p0 = __half22float2(*(__half2*)&u0.x);
        float2 p1 = __half22float2(*(__half2*)&u0.y);
        a0 += w0 * p0.x; a1 += w0 * p0.y; a2 += w0 * p1.x; a3 += w0 * p1.y;
    }
    float4 bb = __ldg((const float4*)(b1 + fb));
    float v0 = fmaxf(a0 + bb.x, 0.f);
    float v1 = fmaxf(a1 + bb.y, 0.f);
    float v2 = fmaxf(a2 + bb.z, 0.f);
    float v3 = fmaxf(a3 + bb.w, 0.f);

    __half h0 = __float2half(v0), h1 = __float2half(v1);
    __half h2 = __float2half(v2), h3 = __float2half(v3);
    uint2 hv = make_uint2(pack_h2(h0, h1), pack_h2(h2, h3));
    __half l0 = __float2half(v0 - __half2float(h0));
    __half l1 = __float2half(v1 - __half2float(h1));
    __half l2 = __float2half(v2 - __half2float(h2));
    __half l3 = __float2half(v3 - __half2float(h3));
    uint2 lv = make_uint2(pack_h2(l0, l1), pack_h2(l2, l3));

    size_t base = (size_t)node * K2EXT;
    *(uint2*)(g_A2 + base + fb)        = hv;
    *(uint2*)(g_A2 + base + NHID + fb) = lv;
}

// ---------------- SpMM layer 2 fused with bias + log_softmax ----------------
// 16 nodes per 256-thread block; 16 threads per node, 4 fp16 classes each.
__global__ __launch_bounds__(256) void spmm2_lsm_k(const float* __restrict__ b2,
                                                   float* __restrict__ out) {
    int t = threadIdx.x;
    int node = blockIdx.x * 16 + (t >> 4);
    int fb = (t & 15) * 4;
    int s = g_row_ptr[node], e = g_row_ptr[node + 1];

    float a0 = 0.f, a1 = 0.f, a2 = 0.f, a3 = 0.f;
    int i = s;
    for (; i + 2 <= e; i += 2) {
        int   s0 = __ldg(&g_src_sorted[i]);
        int   s1 = __ldg(&g_src_sorted[i + 1]);
        float w0 = __ldg(&g_w_sorted[i]);
        float w1 = __ldg(&g_w_sorted[i + 1]);
        uint2 u0 = __ldg((const uint2*)(g_HW2 + (size_t)s0 * NCLASS + fb));
        uint2 u1 = __ldg((const uint2*)(g_HW2 + (size_t)s1 * NCLASS + fb));
        float2 p0 = __half22float2(*(__half2*)&u0.x);
        float2 p1 = __half22float2(*(__half2*)&u0.y);
        a0 += w0 * p0.x; a1 += w0 * p0.y; a2 += w0 * p1.x; a3 += w0 * p1.y;
        float2 q0 = __half22float2(*(__half2*)&u1.x);
        float2 q1 = __half22float2(*(__half2*)&u1.y);
        a0 += w1 * q0.x; a1 += w1 * q0.y; a2 += w1 * q1.x; a3 += w1 * q1.y;
    }
    if (i < e) {
        int   s0 = __ldg(&g_src_sorted[i]);
        float w0 = __ldg(&g_w_sorted[i]);
        uint2 u0 = __ldg((const uint2*)(g_HW2 + (size_t)s0 * NCLASS + fb));
        float2 p0 = __half22float2(*(__half2*)&u0.x);
        float2 p1 = __half22float2(*(__half2*)&u0.y);
        a0 += w0 * p0.x; a1 += w0 * p0.y; a2 += w0 * p1.x; a3 += w0 * p1.y;
    }
    float4 bb = __ldg((const float4*)(b2 + fb));
    float4 lg = make_float4(a0 + bb.x, a1 + bb.y, a2 + bb.z, a3 + bb.w);

    float m = fmaxf(fmaxf(lg.x, lg.y), fmaxf(lg.z, lg.w));
#pragma unroll
    for (int o = 8; o > 0; o >>= 1)
        m = fmaxf(m, __shfl_xor_sync(0xffffffffu, m, o));

    float ex = __expf(lg.x - m) + __expf(lg.y - m)
             + __expf(lg.z - m) + __expf(lg.w - m);
#pragma unroll
    for (int o = 8; o > 0; o >>= 1)
        ex += __shfl_xor_sync(0xffffffffu, ex, o);

    float lz = m + __logf(ex);
    float4 r = make_float4(lg.x - lz, lg.y - lz, lg.z - lz, lg.w - lz);
    *(float4*)(out + (size_t)node * NCLASS + fb) = r;
}

// ---------------- launch ----------------------------------------------------
extern "C" void kernel_launch(void* const* d_in, const int* in_sizes, int n_in,
                              void* d_out, int out_size) {
    const float* x    = (const float*)d_in[0];
    const float* W1   = (const float*)d_in[1];
    const float* b1   = (const float*)d_in[2];
    const float* W2   = (const float*)d_in[3];
    const float* b2   = (const float*)d_in[4];
    const float* ew   = (const float*)d_in[5];
    const int*   esrc = (const int*)d_in[6];
    const int*   edst = (const int*)d_in[7];
    float* out = (float*)d_out;

    __half *dB1, *dA2, *dB2, *dXW1, *dHW2;
    cudaGetSymbolAddress((void**)&dB1, g_B1);
    cudaGetSymbolAddress((void**)&dA2, g_A2);
    cudaGetSymbolAddress((void**)&dB2, g_B2);
    cudaGetSymbolAddress((void**)&dXW1, g_XW1);
    cudaGetSymbolAddress((void**)&dHW2, g_HW2);

    const int SMEM_G1 = 20480 + 2 * 20480;   // 61440
    static bool s_init = false;
    static cudaStream_t s_csr;
    static cudaEvent_t ev_root, ev_csr;
    if (!s_init) {
        cudaFuncSetAttribute(gemm1_fused_k,
                             cudaFuncAttributeMaxDynamicSharedMemorySize, SMEM_G1);
        cudaStreamCreateWithFlags(&s_csr, cudaStreamNonBlocking);
        cudaEventCreateWithFlags(&ev_root, cudaEventDisableTiming);
        cudaEventCreateWithFlags(&ev_csr, cudaEventDisableTiming);
        s_init = true;
    }

    // fork: CSR build on side stream (independent of the GEMM chain)
    cudaEventRecord(ev_root, 0);
    cudaStreamWaitEvent(s_csr, ev_root, 0);
    zero_counts_k<<<(N_NODES + 255) / 256, 256, 0, s_csr>>>();
    hist_k<<<(N_EDGES + 255) / 256, 256, 0, s_csr>>>(edst);
    scan_k<<<1, 1024, 0, s_csr>>>();
    scatter_k<<<(N_EDGES + 255) / 256, 256, 0, s_csr>>>(esrc, edst, ew);
    cudaEventRecord(ev_csr, s_csr);

    // main chain
    conv_w1_k<<<(NFEAT * NHID + 255) / 256, 256>>>(W1);
    conv_w2_k<<<(NHID * NCLASS + 255) / 256, 256>>>(W2);
    gemm1_fused_k<<<M_PAD / 128, 512, SMEM_G1>>>(x, dB1, dXW1);

    // join: spmm needs CSR
    cudaStreamWaitEvent(0, ev_csr, 0);
    spmm1_k<<<N_NODES / 4, 256>>>(b1);
    gemm2_k<<<M_PAD / 128, 256>>>(dA2, dB2, dHW2);
    spmm2_lsm_k<<<N_NODES / 16, 256>>>(b2, out);
}

// round 8
// speedup vs baseline: 3.3597x; 1.0646x over previous
#include <cuda_runtime.h>
#include <cuda_fp16.h>
#include <cstdint>

#define N_NODES 50000
#define M_PAD   50048      // 391 * 128
#define N_EDGES 800000
#define NFEAT   512
#define NHID    256
#define NCLASS  64

// ---------------- scratch (static device globals; no runtime allocation) ----
__device__ __align__(256) __half g_B1[(size_t)NHID * NFEAT];     // [n][k] = fp16(W1[k][n])
__device__ __align__(256) __half g_A2[(size_t)M_PAD * NHID];     // 26 MB (H, fp16)
__device__ __align__(256) __half g_B2[(size_t)NCLASS * NHID];    // [n][k] = fp16(W2[k][n])
__device__ __align__(256) __half g_XW1[(size_t)N_NODES * NHID];  // 26 MB
__device__ __align__(256) __half g_HW2[(size_t)N_NODES * NCLASS];// 6.4 MB
__device__ int   g_counts [N_NODES];
__device__ int   g_row_ptr[N_NODES + 1];
__device__ int   g_cursor [N_NODES];
__device__ int   g_src_sorted[N_EDGES];
__device__ float g_w_sorted  [N_EDGES];

// ---------------- helpers ---------------------------------------------------
__device__ __forceinline__ uint32_t smem_u32(const void* p) {
    uint32_t a;
    asm("{ .reg .u64 t; cvta.to.shared.u64 t, %1; cvt.u32.u64 %0, t; }"
        : "=r"(a) : "l"(p));
    return a;
}
__device__ __forceinline__ uint32_t pack_h2(__half a, __half b) {
    __half2 p(a, b);
    return *(uint32_t*)&p;
}

// ---------------- CSR build -------------------------------------------------
__global__ void zero_counts_k() {
    int i = blockIdx.x * blockDim.x + threadIdx.x;
    if (i * 4 < N_NODES) {
        int4 z = make_int4(0, 0, 0, 0);
        *(int4*)(g_counts + i * 4) = z;
    }
}

// 4 edges per thread: 4 independent atomics -> 4x MLP on the ATOMG latency
__global__ void hist_k(const int4* __restrict__ edst4) {
    int i = blockIdx.x * blockDim.x + threadIdx.x;
    if (i < N_EDGES / 4) {
        int4 d = __ldg(&edst4[i]);
        atomicAdd(&g_counts[d.x], 1);
        atomicAdd(&g_counts[d.y], 1);
        atomicAdd(&g_counts[d.z], 1);
        atomicAdd(&g_counts[d.w], 1);
    }
}

__global__ __launch_bounds__(1024) void scan_k() {
    __shared__ int part[1024];
    const int CH = 49;
    int t = threadIdx.x;
    int begin = t * CH;
    int end = begin + CH; if (end > N_NODES) end = N_NODES;
    int s = 0;
    for (int i = begin; i < end; i++) s += g_counts[i];
    part[t] = s;
    __syncthreads();
    for (int off = 1; off < 1024; off <<= 1) {
        int v = (t >= off) ? part[t - off] : 0;
        __syncthreads();
        part[t] += v;
        __syncthreads();
    }
    int run = (t == 0) ? 0 : part[t - 1];
    for (int i = begin; i < end; i++) {
        g_row_ptr[i] = run;
        g_cursor[i]  = run;
        run += g_counts[i];
    }
    if (t == 1023) g_row_ptr[N_NODES] = part[1023];
}

__global__ void scatter_k(const int4* __restrict__ esrc4,
                          const int4* __restrict__ edst4,
                          const float4* __restrict__ ew4) {
    int i = blockIdx.x * blockDim.x + threadIdx.x;
    if (i < N_EDGES / 4) {
        int4   sv = __ldg(&esrc4[i]);
        int4   dv = __ldg(&edst4[i]);
        float4 wv = __ldg(&ew4[i]);
        int p0 = atomicAdd(&g_cursor[dv.x], 1);
        int p1 = atomicAdd(&g_cursor[dv.y], 1);
        int p2 = atomicAdd(&g_cursor[dv.z], 1);
        int p3 = atomicAdd(&g_cursor[dv.w], 1);
        g_src_sorted[p0] = sv.x; g_w_sorted[p0] = wv.x;
        g_src_sorted[p1] = sv.y; g_w_sorted[p1] = wv.y;
        g_src_sorted[p2] = sv.z; g_w_sorted[p2] = wv.z;
        g_src_sorted[p3] = sv.w; g_w_sorted[p3] = wv.w;
    }
}

// ---------------- weight conversions ----------------------------------------
__global__ void conv_w1_k(const float* __restrict__ W1) {
    int i = blockIdx.x * blockDim.x + threadIdx.x;
    if (i >= NFEAT * NHID) return;
    int k = i / NHID, n = i - k * NHID;
    g_B1[(size_t)n * NFEAT + k] = __float2half(W1[i]);
}

__global__ void conv_w2_k(const float* __restrict__ W2) {
    int i = blockIdx.x * blockDim.x + threadIdx.x;
    if (i >= NHID * NCLASS) return;
    int k = i / NCLASS, n = i - k * NCLASS;
    g_B2[(size_t)n * NHID + k] = __float2half(W2[i]);
}

// ---------------- GEMM1 fused: XW1 = x @ W1, fp16 single-term ---------------
// BM=128, BN=256 (all columns), 512 threads = 16 warps (4x4), warp tile 32x64.
// smem: A[0,10240) ; B buf b at 10240+b*20480
__global__ __launch_bounds__(512, 1) void gemm1_fused_k(const float* __restrict__ x,
                                                        const __half* __restrict__ B1,
                                                        __half* __restrict__ C) {
    constexpr int STRIDE_B = 80;
    constexpr int NCH = NFEAT / 32;   // 16
    extern __shared__ char smem[];
    uint32_t sa = smem_u32(smem);

    int tid = threadIdx.x, warp = tid >> 5, lane = tid & 31;
    int m0 = blockIdx.x * 128;
    int wm = warp & 3, wn = warp >> 2;          // 4 x 4 warps
    int wm0 = wm * 32, wn0 = wn * 64;

    // A loader: 4 threads per row, 8 floats each
    int r = tid >> 2, q = tid & 3;
    bool rowok = (m0 + r) < N_NODES;
    const float* xrow = x + (size_t)(m0 + r) * NFEAT + q * 8;

    const char* Bgl = (const char*)B1;

    auto load_B = [&](int c, int buf) {
        uint32_t bb = sa + 10240 + buf * 20480;
#pragma unroll
        for (int u = 0; u < 2; u++) {
            int idx = u * 512 + tid;
            int row = idx >> 2, qq = idx & 3;
            uint32_t dst = bb + row * STRIDE_B + qq * 16;
            const void* src = Bgl + (size_t)row * 1024 + c * 64 + qq * 16;
            asm volatile("cp.async.cg.shared.global [%0], [%1], 16;"
                         :: "r"(dst), "l"(src));
        }
        asm volatile("cp.async.commit_group;");
    };

    float4 pf[2];
#pragma unroll
    for (int j = 0; j < 2; j++)
        pf[j] = rowok ? *(const float4*)(xrow + j * 4)
                      : make_float4(0.f, 0.f, 0.f, 0.f);
    load_B(0, 0);

    float acc[2][8][4];
#pragma unroll
    for (int i = 0; i < 2; i++)
#pragma unroll
        for (int j = 0; j < 8; j++)
#pragma unroll
            for (int p = 0; p < 4; p++) acc[i][j][p] = 0.f;

    for (int c = 0; c < NCH; c++) {
        // convert + store A(c) tile
        {
            char* base = smem + r * STRIDE_B + q * 16;
            __half h[8];
#pragma unroll
            for (int j = 0; j < 2; j++) {
                float4 v = pf[j];
                h[j*4+0] = __float2half(v.x);
                h[j*4+1] = __float2half(v.y);
                h[j*4+2] = __float2half(v.z);
                h[j*4+3] = __float2half(v.w);
            }
            uint4 hv = make_uint4(pack_h2(h[0],h[1]), pack_h2(h[2],h[3]),
                                  pack_h2(h[4],h[5]), pack_h2(h[6],h[7]));
            *(uint4*)base = hv;
        }
        if (c + 1 < NCH) {
#pragma unroll
            for (int j = 0; j < 2; j++)
                pf[j] = rowok ? *(const float4*)(xrow + (c + 1) * 32 + j * 4)
                              : make_float4(0.f, 0.f, 0.f, 0.f);
            load_B(c + 1, (c + 1) & 1);
            asm volatile("cp.async.wait_group 1;");
        } else {
            asm volatile("cp.async.wait_group 0;");
        }
        __syncthreads();

        uint32_t aH = sa;
        uint32_t bH = sa + 10240 + (c & 1) * 20480;
#pragma unroll
        for (int kk = 0; kk < 2; kk++) {
            uint32_t af[2][4];
#pragma unroll
            for (int mt = 0; mt < 2; mt++) {
                uint32_t addr = aH + (wm0 + mt * 16 + (lane & 15)) * STRIDE_B
                              + kk * 32 + (lane >> 4) * 16;
                asm volatile(
                    "ldmatrix.sync.aligned.m8n8.x4.shared.b16 {%0,%1,%2,%3}, [%4];"
                    : "=r"(af[mt][0]), "=r"(af[mt][1]),
                      "=r"(af[mt][2]), "=r"(af[mt][3]) : "r"(addr));
            }
#pragma unroll
            for (int nh = 0; nh < 2; nh++) {     // two 32-col halves of warp N
                uint32_t bf[4][2];
#pragma unroll
                for (int nb = 0; nb < 2; nb++) {
                    int nrow = wn0 + nh * 32 + nb * 16
                             + (lane & 7) + ((lane >> 4) & 1) * 8;
                    int khalf = (lane >> 3) & 1;
                    uint32_t adH = bH + nrow * STRIDE_B + kk * 32 + khalf * 16;
                    asm volatile(
                        "ldmatrix.sync.aligned.m8n8.x4.shared.b16 {%0,%1,%2,%3}, [%4];"
                        : "=r"(bf[nb * 2][0]), "=r"(bf[nb * 2][1]),
                          "=r"(bf[nb * 2 + 1][0]), "=r"(bf[nb * 2 + 1][1])
                        : "r"(adH));
                }
#pragma unroll
                for (int mt = 0; mt < 2; mt++)
#pragma unroll
                    for (int nt = 0; nt < 4; nt++)
                        asm volatile(
                            "mma.sync.aligned.m16n8k16.row.col.f32.f16.f16.f32 "
                            "{%0,%1,%2,%3}, {%4,%5,%6,%7}, {%8,%9}, {%0,%1,%2,%3};"
                            : "+f"(acc[mt][nh*4+nt][0]), "+f"(acc[mt][nh*4+nt][1]),
                              "+f"(acc[mt][nh*4+nt][2]), "+f"(acc[mt][nh*4+nt][3])
                            : "r"(af[mt][0]), "r"(af[mt][1]),
                              "r"(af[mt][2]), "r"(af[mt][3]),
                              "r"(bf[nt][0]), "r"(bf[nt][1]));
            }
        }
        __syncthreads();
    }

    // epilogue: fp16 output
#pragma unroll
    for (int mt = 0; mt < 2; mt++) {
        int r0 = m0 + wm0 + mt * 16 + (lane >> 2);
#pragma unroll
        for (int nt = 0; nt < 8; nt++) {
            int cc = wn0 + nt * 8 + (lane & 3) * 2;
            if (r0 < N_NODES)
                *(uint32_t*)(C + (size_t)r0 * NHID + cc) =
                    pack_h2(__float2half(acc[mt][nt][0]),
                            __float2half(acc[mt][nt][1]));
            if (r0 + 8 < N_NODES)
                *(uint32_t*)(C + (size_t)(r0 + 8) * NHID + cc) =
                    pack_h2(__float2half(acc[mt][nt][2]),
                            __float2half(acc[mt][nt][3]));
        }
    }
}

// ---------------- GEMM2: HW2 = A2 @ B2^T (fp16, K=256, BN=64) ---------------
__global__ __launch_bounds__(256) void gemm2_k(const __half* __restrict__ A,
                                               const __half* __restrict__ Bm,
                                               __half* __restrict__ C) {
    constexpr int BM = 128, BN = 64, BK = 32, KK = NHID;
    constexpr int STRIDE_B = 80;
    constexpr int A_BUF = BM * STRIDE_B;   // 10240
    constexpr int B_BUF = BN * STRIDE_B;   // 5120
    constexpr int NC = KK / BK;            // 8

    __shared__ char smem[2 * (A_BUF + B_BUF)];
    uint32_t sa = smem_u32(smem);
    uint32_t sbB = sa + 2 * A_BUF;

    int tid = threadIdx.x, warp = tid >> 5, lane = tid & 31;
    int m0 = blockIdx.x * BM;
    int wm = warp & 3, wn = warp >> 2;     // 4 x 2
    int wm0 = wm * 32, wn0 = wn * 32;

    const char* Agl = (const char*)(A + (size_t)m0 * KK);
    const char* Bgl = (const char*)Bm;

    auto load_tile = [&](int c, int buf) {
        int koff = c * BK * 2;
        uint32_t ad = sa + buf * A_BUF;
#pragma unroll
        for (int u = 0; u < 2; u++) {
            int idx = u * 256 + tid;
            int r = idx >> 2, ch = idx & 3;
            uint32_t dst = ad + r * STRIDE_B + ch * 16;
            const void* src = Agl + (size_t)r * (KK * 2) + koff + ch * 16;
            asm volatile("cp.async.cg.shared.global [%0], [%1], 16;"
                         :: "r"(dst), "l"(src));
        }
        uint32_t bd = sbB + buf * B_BUF;
        {
            int r = tid >> 2, ch = tid & 3;
            if (r < BN) {
                uint32_t dst = bd + r * STRIDE_B + ch * 16;
                const void* src = Bgl + (size_t)r * (KK * 2) + koff + ch * 16;
                asm volatile("cp.async.cg.shared.global [%0], [%1], 16;"
                             :: "r"(dst), "l"(src));
            }
        }
        asm volatile("cp.async.commit_group;");
    };

    float acc[2][4][4];
#pragma unroll
    for (int i = 0; i < 2; i++)
#pragma unroll
        for (int j = 0; j < 4; j++)
#pragma unroll
            for (int p = 0; p < 4; p++) acc[i][j][p] = 0.f;

    load_tile(0, 0);

    for (int c = 0; c < NC; c++) {
        int buf = c & 1;
        if (c + 1 < NC) {
            load_tile(c + 1, buf ^ 1);
            asm volatile("cp.async.wait_group 1;");
        } else {
            asm volatile("cp.async.wait_group 0;");
        }
        __syncthreads();

        uint32_t abase = sa + buf * A_BUF;
        uint32_t bbase = sbB + buf * B_BUF;
#pragma unroll
        for (int kk = 0; kk < 2; kk++) {
            uint32_t af[2][4];
#pragma unroll
            for (int mt = 0; mt < 2; mt++) {
                uint32_t addr = abase
                    + (wm0 + mt * 16 + (lane & 15)) * STRIDE_B
                    + kk * 32 + (lane >> 4) * 16;
                asm volatile(
                    "ldmatrix.sync.aligned.m8n8.x4.shared.b16 {%0,%1,%2,%3}, [%4];"
                    : "=r"(af[mt][0]), "=r"(af[mt][1]),
                      "=r"(af[mt][2]), "=r"(af[mt][3])
                    : "r"(addr));
            }
            uint32_t bf[4][2];
#pragma unroll
            for (int nb = 0; nb < 2; nb++) {
                int nrow = wn0 + nb * 16 + (lane & 7) + ((lane >> 4) & 1) * 8;
                int khalf = (lane >> 3) & 1;
                uint32_t addr = bbase + nrow * STRIDE_B + kk * 32 + khalf * 16;
                asm volatile(
                    "ldmatrix.sync.aligned.m8n8.x4.shared.b16 {%0,%1,%2,%3}, [%4];"
                    : "=r"(bf[nb * 2][0]), "=r"(bf[nb * 2][1]),
                      "=r"(bf[nb * 2 + 1][0]), "=r"(bf[nb * 2 + 1][1])
                    : "r"(addr));
            }
#pragma unroll
            for (int mt = 0; mt < 2; mt++)
#pragma unroll
                for (int nt = 0; nt < 4; nt++) {
                    asm volatile(
                        "mma.sync.aligned.m16n8k16.row.col.f32.f16.f16.f32 "
                        "{%0,%1,%2,%3}, {%4,%5,%6,%7}, {%8,%9}, {%0,%1,%2,%3};"
                        : "+f"(acc[mt][nt][0]), "+f"(acc[mt][nt][1]),
                          "+f"(acc[mt][nt][2]), "+f"(acc[mt][nt][3])
                        : "r"(af[mt][0]), "r"(af[mt][1]),
                          "r"(af[mt][2]), "r"(af[mt][3]),
                          "r"(bf[nt][0]), "r"(bf[nt][1]));
                }
        }
        __syncthreads();
    }

#pragma unroll
    for (int mt = 0; mt < 2; mt++) {
        int r0 = m0 + wm0 + mt * 16 + (lane >> 2);
#pragma unroll
        for (int nt = 0; nt < 4; nt++) {
            int cc = wn0 + nt * 8 + (lane & 3) * 2;
            if (r0 < N_NODES)
                *(uint32_t*)(C + (size_t)r0 * NCLASS + cc) =
                    pack_h2(__float2half(acc[mt][nt][0]),
                            __float2half(acc[mt][nt][1]));
            if (r0 + 8 < N_NODES)
                *(uint32_t*)(C + (size_t)(r0 + 8) * NCLASS + cc) =
                    pack_h2(__float2half(acc[mt][nt][2]),
                            __float2half(acc[mt][nt][3]));
        }
    }
}

// ---------------- SpMM layer 1: A2 = fp16(relu(A @ XW1 + b1)) ---------------
// 4 nodes per 256-thread block; 64 threads per node, 4 fp16 feats per thread.
__global__ __launch_bounds__(256) void spmm1_k(const float* __restrict__ b1) {
    int t = threadIdx.x;
    int node = blockIdx.x * 4 + (t >> 6);
    int fb = (t & 63) * 4;
    int s = g_row_ptr[node], e = g_row_ptr[node + 1];

    float a0 = 0.f, a1 = 0.f, a2 = 0.f, a3 = 0.f;
    int i = s;
    for (; i + 2 <= e; i += 2) {
        int   s0 = __ldg(&g_src_sorted[i]);
        int   s1 = __ldg(&g_src_sorted[i + 1]);
        float w0 = __ldg(&g_w_sorted[i]);
        float w1 = __ldg(&g_w_sorted[i + 1]);
        uint2 u0 = __ldg((const uint2*)(g_XW1 + (size_t)s0 * NHID + fb));
        uint2 u1 = __ldg((const uint2*)(g_XW1 + (size_t)s1 * NHID + fb));
        float2 p0 = __half22float2(*(__half2*)&u0.x);
        float2 p1 = __half22float2(*(__half2*)&u0.y);
        a0 += w0 * p0.x; a1 += w0 * p0.y; a2 += w0 * p1.x; a3 += w0 * p1.y;
        float2 q0 = __half22float2(*(__half2*)&u1.x);
        float2 q1 = __half22float2(*(__half2*)&u1.y);
        a0 += w1 * q0.x; a1 += w1 * q0.y; a2 += w1 * q1.x; a3 += w1 * q1.y;
    }
    if (i < e) {
        int   s0 = __ldg(&g_src_sorted[i]);
        float w0 = __ldg(&g_w_sorted[i]);
        uint2 u0 = __ldg((const uint2*)(g_XW1 + (size_t)s0 * NHID + fb));
        float2 p0 = __half22float2(*(__half2*)&u0.x);
        float2 p1 = __half22float2(*(__half2*)&u0.y);
        a0 += w0 * p0.x; a1 += w0 * p0.y; a2 += w0 * p1.x; a3 += w0 * p1.y;
    }
    float4 bb = __ldg((const float4*)(b1 + fb));
    float v0 = fmaxf(a0 + bb.x, 0.f);
    float v1 = fmaxf(a1 + bb.y, 0.f);
    float v2 = fmaxf(a2 + bb.z, 0.f);
    float v3 = fmaxf(a3 + bb.w, 0.f);

    uint2 hv = make_uint2(pack_h2(__float2half(v0), __float2half(v1)),
                          pack_h2(__float2half(v2), __float2half(v3)));
    *(uint2*)(g_A2 + (size_t)node * NHID + fb) = hv;
}

// ---------------- SpMM layer 2 fused with bias + log_softmax ----------------
// 16 nodes per 256-thread block; 16 threads per node, 4 fp16 classes each.
__global__ __launch_bounds__(256) void spmm2_lsm_k(const float* __restrict__ b2,
                                                   float* __restrict__ out) {
    int t = threadIdx.x;
    int node = blockIdx.x * 16 + (t >> 4);
    int fb = (t & 15) * 4;
    int s = g_row_ptr[node], e = g_row_ptr[node + 1];

    float a0 = 0.f, a1 = 0.f, a2 = 0.f, a3 = 0.f;
    int i = s;
    for (; i + 2 <= e; i += 2) {
        int   s0 = __ldg(&g_src_sorted[i]);
        int   s1 = __ldg(&g_src_sorted[i + 1]);
        float w0 = __ldg(&g_w_sorted[i]);
        float w1 = __ldg(&g_w_sorted[i + 1]);
        uint2 u0 = __ldg((const uint2*)(g_HW2 + (size_t)s0 * NCLASS + fb));
        uint2 u1 = __ldg((const uint2*)(g_HW2 + (size_t)s1 * NCLASS + fb));
        float2 p0 = __half22float2(*(__half2*)&u0.x);
        float2 p1 = __half22float2(*(__half2*)&u0.y);
        a0 += w0 * p0.x; a1 += w0 * p0.y; a2 += w0 * p1.x; a3 += w0 * p1.y;
        float2 q0 = __half22float2(*(__half2*)&u1.x);
        float2 q1 = __half22float2(*(__half2*)&u1.y);
        a0 += w1 * q0.x; a1 += w1 * q0.y; a2 += w1 * q1.x; a3 += w1 * q1.y;
    }
    if (i < e) {
        int   s0 = __ldg(&g_src_sorted[i]);
        float w0 = __ldg(&g_w_sorted[i]);
        uint2 u0 = __ldg((const uint2*)(g_HW2 + (size_t)s0 * NCLASS + fb));
        float2 p0 = __half22float2(*(__half2*)&u0.x);
        float2 p1 = __half22float2(*(__half2*)&u0.y);
        a0 += w0 * p0.x; a1 += w0 * p0.y; a2 += w0 * p1.x; a3 += w0 * p1.y;
    }
    float4 bb = __ldg((const float4*)(b2 + fb));
    float4 lg = make_float4(a0 + bb.x, a1 + bb.y, a2 + bb.z, a3 + bb.w);

    float m = fmaxf(fmaxf(lg.x, lg.y), fmaxf(lg.z, lg.w));
#pragma unroll
    for (int o = 8; o > 0; o >>= 1)
        m = fmaxf(m, __shfl_xor_sync(0xffffffffu, m, o));

    float ex = __expf(lg.x - m) + __expf(lg.y - m)
             + __expf(lg.z - m) + __expf(lg.w - m);
#pragma unroll
    for (int o = 8; o > 0; o >>= 1)
        ex += __shfl_xor_sync(0xffffffffu, ex, o);

    float lz = m + __logf(ex);
    float4 rr = make_float4(lg.x - lz, lg.y - lz, lg.z - lz, lg.w - lz);
    *(float4*)(out + (size_t)node * NCLASS + fb) = rr;
}

// ---------------- launch ----------------------------------------------------
extern "C" void kernel_launch(void* const* d_in, const int* in_sizes, int n_in,
                              void* d_out, int out_size) {
    const float* x    = (const float*)d_in[0];
    const float* W1   = (const float*)d_in[1];
    const float* b1   = (const float*)d_in[2];
    const float* W2   = (const float*)d_in[3];
    const float* b2   = (const float*)d_in[4];
    const float* ew   = (const float*)d_in[5];
    const int*   esrc = (const int*)d_in[6];
    const int*   edst = (const int*)d_in[7];
    float* out = (float*)d_out;

    __half *dB1, *dA2, *dB2, *dXW1, *dHW2;
    cudaGetSymbolAddress((void**)&dB1, g_B1);
    cudaGetSymbolAddress((void**)&dA2, g_A2);
    cudaGetSymbolAddress((void**)&dB2, g_B2);
    cudaGetSymbolAddress((void**)&dXW1, g_XW1);
    cudaGetSymbolAddress((void**)&dHW2, g_HW2);

    const int SMEM_G1 = 10240 + 2 * 20480;   // 51200
    static bool s_init = false;
    static cudaStream_t s_csr;
    static cudaEvent_t ev_root, ev_csr;
    if (!s_init) {
        cudaFuncSetAttribute(gemm1_fused_k,
                             cudaFuncAttributeMaxDynamicSharedMemorySize, SMEM_G1);
        cudaStreamCreateWithFlags(&s_csr, cudaStreamNonBlocking);
        cudaEventCreateWithFlags(&ev_root, cudaEventDisableTiming);
        cudaEventCreateWithFlags(&ev_csr, cudaEventDisableTiming);
        s_init = true;
    }

    // fork: CSR build on side stream (independent of the GEMM chain)
    cudaEventRecord(ev_root, 0);
    cudaStreamWaitEvent(s_csr, ev_root, 0);
    zero_counts_k<<<(N_NODES / 4 + 255) / 256, 256, 0, s_csr>>>();
    hist_k<<<(N_EDGES / 4 + 255) / 256, 256, 0, s_csr>>>((const int4*)edst);
    scan_k<<<1, 1024, 0, s_csr>>>();
    scatter_k<<<(N_EDGES / 4 + 255) / 256, 256, 0, s_csr>>>(
        (const int4*)esrc, (const int4*)edst, (const float4*)ew);
    cudaEventRecord(ev_csr, s_csr);

    // main chain
    conv_w1_k<<<(NFEAT * NHID + 255) / 256, 256>>>(W1);
    conv_w2_k<<<(NHID * NCLASS + 255) / 256, 256>>>(W2);
    gemm1_fused_k<<<M_PAD / 128, 512, SMEM_G1>>>(x, dB1, dXW1);

    // join: spmm needs CSR
    cudaStreamWaitEvent(0, ev_csr, 0);
    spmm1_k<<<N_NODES / 4, 256>>>(b1);
    gemm2_k<<<M_PAD / 128, 256>>>(dA2, dB2, dHW2);
    spmm2_lsm_k<<<N_NODES / 16, 256>>>(b2, out);
}